// round 4
// baseline (speedup 1.0000x reference)
#include <cuda_runtime.h>
#include <math.h>

#define T_ 64
#define B_ 128
#define H_ 512
#define A_ 3
#define L_ 5
#define Z_ 512
#define NH4 (4*H_)      /* 2048 */
#define N3Z (3*Z_)      /* 1536 */
#define LZ  (L_*Z_)     /* 2560 */

#define BM 64
#define BN 64
#define BK 16

// ---------------- persistent scratch (device globals; no allocation) -------
__device__ float g_hs[L_*A_*B_*H_];          // (l,a,b,h) hidden state
__device__ float g_cs[L_*A_*B_*H_];          // (l,a,b,h) cell state
__device__ float g_hg[B_*H_];                // h_g carry (B,H)
__device__ float g_pre[A_*B_*NH4];           // LSTM pre-activations (a,b,g*H+o)
__device__ float g_pre3[L_*A_*B_*N3Z];       // cell_fn pre (l,a,b,g*Z+z)
__device__ float g_icell[L_*A_*B_*Z_];
__device__ float g_ccell[L_*A_*B_*Z_];
__device__ float g_t1p[L_*A_*B_*Z_];         // per-(l,a) partials (deterministic)
__device__ float g_t2p[L_*A_*B_*Z_];
__device__ float g_hgp[4*B_*H_];             // single_li split-K partials
__device__ float g_cat[B_*LZ];

// ---------------- grid barrier ---------------------------------------------
__device__ unsigned g_cnt = 0;
__device__ volatile unsigned g_gen = 0;

__device__ __forceinline__ void gsync() {
    __syncthreads();
    if (threadIdx.x == 0) {
        unsigned gen = g_gen;
        __threadfence();
        if (atomicAdd(&g_cnt, 1u) == gridDim.x - 1) {
            g_cnt = 0;
            __threadfence();
            g_gen = gen + 1u;
        } else {
            while (g_gen == gen) { __nanosleep(32); }
        }
        __threadfence();
    }
    __syncthreads();
}

__device__ __forceinline__ float sigmoidf_(float x) { return 1.f / (1.f + expf(-x)); }

// ---------------- shared tiled GEMM core (TN: both operands K-contiguous) --
// acc += A[m0+i, :K] . B[n0+j, :K]; lda/ldb row strides; K % 16 == 0.
__device__ __forceinline__ void gemm_tn_pass(
    const float* __restrict__ Aop, int lda,
    const float* __restrict__ Bop, int ldb,
    int K, int m0, int n0,
    float* As, float* Bs, float (&acc)[4][4])
{
    const int tid = threadIdx.x;
    const int tx = tid & 15, ty = tid >> 4;
    const int lr = tid >> 2;          // 0..63: tile row for loads
    const int lk = (tid & 3) << 2;    // 0,4,8,12: k offset for loads
    for (int k0 = 0; k0 < K; k0 += BK) {
        float4 av = *(const float4*)(Aop + (size_t)(m0 + lr) * lda + (k0 + lk));
        float4 bv = *(const float4*)(Bop + (size_t)(n0 + lr) * ldb + (k0 + lk));
        As[(lk+0)*BM + lr] = av.x;
        As[(lk+1)*BM + lr] = av.y;
        As[(lk+2)*BM + lr] = av.z;
        As[(lk+3)*BM + lr] = av.w;
        Bs[(lk+0)*BN + lr] = bv.x;
        Bs[(lk+1)*BN + lr] = bv.y;
        Bs[(lk+2)*BN + lr] = bv.z;
        Bs[(lk+3)*BN + lr] = bv.w;
        __syncthreads();
        #pragma unroll
        for (int kk = 0; kk < BK; ++kk) {
            const float4 a4 = *(const float4*)(As + kk*BM + (ty<<2));
            const float4 b4 = *(const float4*)(Bs + kk*BN + (tx<<2));
            float avr[4] = {a4.x, a4.y, a4.z, a4.w};
            float bvr[4] = {b4.x, b4.y, b4.z, b4.w};
            #pragma unroll
            for (int i = 0; i < 4; ++i)
                #pragma unroll
                for (int j = 0; j < 4; ++j)
                    acc[i][j] = fmaf(avr[i], bvr[j], acc[i][j]);
        }
        __syncthreads();
    }
}

// ---------------- the single persistent kernel ------------------------------
__global__ __launch_bounds__(256, 2) void k_persist(
    const float* __restrict__ x,    const float* __restrict__ Wx,
    const float* __restrict__ Wh,   const float* __restrict__ b_lstm,
    const float* __restrict__ Wg_h, const float* __restrict__ Wg_p,
    const float* __restrict__ bg,   const float* __restrict__ Wilc,
    const float* __restrict__ bilc, const float* __restrict__ Wsl,
    const float* __restrict__ bsl,  const float* __restrict__ Wlin,
    const float* __restrict__ blin, float* __restrict__ out)
{
    __shared__ __align__(16) float sm[3*BK*BM];   // 12 KB, reused per stage
    float* As = sm;
    float* Bs = sm + BK*BM;

    const int P   = gridDim.x;
    const int tid = threadIdx.x;
    const int tx  = tid & 15, ty = tid >> 4;
    const int gthreads = P * 256;
    const int gtid = blockIdx.x * 256 + tid;

    // -------- init states --------
    for (int i = gtid; i < L_*A_*B_*H_; i += gthreads) { g_hs[i] = 0.f; g_cs[i] = 0.f; }
    for (int i = gtid; i < B_*H_; i += gthreads) g_hg[i] = 0.f;
    gsync();

    for (int t = 0; t < T_; ++t) {
        const float* xt = x + (size_t)t * B_ * H_;

        // ===== Multi-LSTM levels =====
        for (int l = 0; l < L_; ++l) {
            // --- GEMM stage: 192 tiles (+16 y-items for step t-1 at l==0) ---
            const int extra = (l == 0 && t > 0) ? 16 : 0;
            for (int w = blockIdx.x; w < 192 + extra; w += P) {
                if (w < 192) {
                    const int a  = w / 64;
                    const int r  = w - a * 64;
                    const int m0 = (r >> 5) * BM;       // r/32 in {0,1}
                    const int n0 = (r & 31) * BN;       // r%32 in 0..31
                    float acc[4][4] = {};
                    const float* inp  = (l == 0) ? xt
                                       : (g_hs + ((size_t)(l-1)*A_ + a) * B_ * H_);
                    const float* hold = g_hs + ((size_t)l*A_ + a) * B_ * H_;
                    const float* wx   = Wx + ((size_t)(a*L_ + l)) * 4 * H_ * H_;
                    const float* wh   = Wh + ((size_t)(a*L_ + l)) * 4 * H_ * H_;
                    gemm_tn_pass(inp,  H_, wx, H_, H_, m0, n0, As, Bs, acc);
                    gemm_tn_pass(hold, H_, wh, H_, H_, m0, n0, As, Bs, acc);
                    float* o = g_pre + (size_t)a * B_ * NH4;
                    #pragma unroll
                    for (int i = 0; i < 4; ++i)
                        #pragma unroll
                        for (int j = 0; j < 4; ++j)
                            o[(size_t)(m0 + (ty<<2) + i) * NH4 + n0 + (tx<<2) + j] = acc[i][j];
                } else {
                    // y for step t-1: item j covers batches 8j..8j+7 (one per warp)
                    const int j    = w - 192;
                    const int warp = tid >> 5, lane = tid & 31;
                    const int b    = j * 8 + warp;
                    const float* h  = g_hg + (size_t)b * H_;
                    const float* wl = Wlin + (size_t)(t-1) * H_;
                    float s = 0.f;
                    for (int k = lane; k < H_; k += 32) s = fmaf(h[k], wl[k], s);
                    #pragma unroll
                    for (int o2 = 16; o2 > 0; o2 >>= 1)
                        s += __shfl_down_sync(0xffffffffu, s, o2);
                    if (lane == 0) out[(size_t)(t-1) * B_ + b] = s + blin[t-1];
                }
            }
            gsync();

            // --- pointwise gates (in place on hs/cs) ---
            for (int idx = gtid; idx < A_*B_*H_; idx += gthreads) {
                int a = idx / (B_*H_);
                int r = idx - a * (B_*H_);
                int b = r / H_;
                int o = r - b * H_;
                size_t base = ((size_t)a * B_ + b) * NH4;
                const float* bb = b_lstm + ((size_t)(a*L_ + l)) * 4 * H_;
                float pi = g_pre[base + 0*H_ + o] + bb[0*H_ + o];
                float pf = g_pre[base + 1*H_ + o] + bb[1*H_ + o];
                float pg = g_pre[base + 2*H_ + o] + bb[2*H_ + o];
                float po = g_pre[base + 3*H_ + o] + bb[3*H_ + o];
                float ig = sigmoidf_(pi);
                float fg = sigmoidf_(pf);
                float gg = tanhf(pg);
                float og = sigmoidf_(po);
                size_t ci = ((size_t)(l*A_ + a) * B_ + b) * H_ + o;
                float c = fg * g_cs[ci] + ig * gg;
                g_cs[ci] = c;
                g_hs[ci] = og * tanhf(c);
            }
            gsync();
        }

        // ===== cell_fn pre GEMM: 720 tiles =====
        for (int w = blockIdx.x; w < 720; w += P) {
            const int la = w / 48;
            const int r  = w - la * 48;
            const int m0 = (r / 24) * BM;
            const int n0 = (r % 24) * BN;
            float acc[4][4] = {};
            gemm_tn_pass(g_hg, H_, Wg_h + (size_t)la * N3Z * H_, H_, H_,
                         m0, n0, As, Bs, acc);
            gemm_tn_pass(g_hs + (size_t)la * B_ * H_, H_,
                         Wg_p + (size_t)la * N3Z * Z_, Z_, Z_, m0, n0, As, Bs, acc);
            float* o = g_pre3 + (size_t)la * B_ * N3Z;
            #pragma unroll
            for (int i = 0; i < 4; ++i)
                #pragma unroll
                for (int j = 0; j < 4; ++j)
                    o[(size_t)(m0 + (ty<<2) + i) * N3Z + n0 + (tx<<2) + j] = acc[i][j];
        }
        gsync();

        // ===== cell_fn pointwise =====
        for (int idx = gtid; idx < L_*A_*B_*Z_; idx += gthreads) {
            int la = idx / (B_*Z_);
            int r  = idx - la * (B_*Z_);
            int z  = r % Z_;
            size_t base = ((size_t)la * B_ + (r / Z_)) * N3Z;
            const float* bb = bg + (size_t)la * N3Z;
            float ig = sigmoidf_(g_pre3[base + 0*Z_ + z] + bb[0*Z_ + z]);
            float fg = sigmoidf_(g_pre3[base + 1*Z_ + z] + bb[1*Z_ + z]);
            float gg = tanhf    (g_pre3[base + 2*Z_ + z] + bb[2*Z_ + z]);
            float ic = ig * g_cs[idx];              // sc: identical (l,a,b,h) layout
            g_icell[idx] = ic;
            g_ccell[idx] = fg * gg + ic;
        }
        gsync();

        // ===== t1/t2 GEMM per (l,a): 240 tiles, deterministic partials =====
        for (int w = blockIdx.x; w < 240; w += P) {
            const int la = w / 16;
            const int r  = w - la * 16;
            const int m0 = (r >> 3) * BM;
            const int n0 = (r & 7) * BN;
            const float* A1 = g_icell + (size_t)la * B_ * Z_;
            const float* A2 = g_ccell + (size_t)la * B_ * Z_;
            const float* W  = Wilc    + (size_t)la * Z_ * Z_;
            float* As1 = sm; float* As2 = sm + BK*BM; float* Bs2 = sm + 2*BK*BM;
            float acc1[4][4] = {}, acc2[4][4] = {};
            const int lr  = tid >> 2, lk = (tid & 3) << 2;   // A loaders (transpose)
            const int bkr = tid >> 4, bnc = (tid & 15) << 2; // B loader (K-major direct)
            for (int k0 = 0; k0 < Z_; k0 += BK) {
                float4 a1 = *(const float4*)(A1 + (size_t)(m0 + lr) * Z_ + k0 + lk);
                float4 a2 = *(const float4*)(A2 + (size_t)(m0 + lr) * Z_ + k0 + lk);
                As1[(lk+0)*BM + lr] = a1.x; As1[(lk+1)*BM + lr] = a1.y;
                As1[(lk+2)*BM + lr] = a1.z; As1[(lk+3)*BM + lr] = a1.w;
                As2[(lk+0)*BM + lr] = a2.x; As2[(lk+1)*BM + lr] = a2.y;
                As2[(lk+2)*BM + lr] = a2.z; As2[(lk+3)*BM + lr] = a2.w;
                float4 bv = *(const float4*)(W + (size_t)(k0 + bkr) * Z_ + n0 + bnc);
                *(float4*)(Bs2 + bkr*BN + bnc) = bv;
                __syncthreads();
                #pragma unroll
                for (int kk = 0; kk < BK; ++kk) {
                    const float4 a14 = *(const float4*)(As1 + kk*BM + (ty<<2));
                    const float4 a24 = *(const float4*)(As2 + kk*BM + (ty<<2));
                    const float4 b4  = *(const float4*)(Bs2 + kk*BN + (tx<<2));
                    float u[4] = {a14.x,a14.y,a14.z,a14.w};
                    float v[4] = {a24.x,a24.y,a24.z,a24.w};
                    float wv[4] = {b4.x,b4.y,b4.z,b4.w};
                    #pragma unroll
                    for (int i = 0; i < 4; ++i)
                        #pragma unroll
                        for (int j = 0; j < 4; ++j) {
                            acc1[i][j] = fmaf(u[i], wv[j], acc1[i][j]);
                            acc2[i][j] = fmaf(v[i], wv[j], acc2[i][j]);
                        }
                }
                __syncthreads();
            }
            float* o1 = g_t1p + (size_t)la * B_ * Z_;
            float* o2 = g_t2p + (size_t)la * B_ * Z_;
            #pragma unroll
            for (int i = 0; i < 4; ++i)
                #pragma unroll
                for (int j = 0; j < 4; ++j) {
                    size_t oi = (size_t)(m0 + (ty<<2) + i) * Z_ + n0 + (tx<<2) + j;
                    o1[oi] = acc1[i][j];
                    o2[oi] = acc2[i][j];
                }
        }
        gsync();

        // ===== combine: axis-sum + bias, sigmoid(t2)*softmax(t1) -> cat =====
        for (int row = blockIdx.x; row < L_*B_; row += P) {
            const int l = row / B_, b = row % B_;
            float t1v[2], t2v[2];
            #pragma unroll
            for (int h = 0; h < 2; ++h) {
                const int y = tid + h*256;
                float sb = bilc[(size_t)(l*A_+0)*Z_ + y]
                         + bilc[(size_t)(l*A_+1)*Z_ + y]
                         + bilc[(size_t)(l*A_+2)*Z_ + y];
                size_t off = (size_t)b * Z_ + y;
                size_t st  = (size_t)B_ * Z_;
                const float* p1 = g_t1p + (size_t)(l*A_) * st + off;
                const float* p2 = g_t2p + (size_t)(l*A_) * st + off;
                t1v[h] = p1[0] + p1[st] + p1[2*st] + sb;
                t2v[h] = p2[0] + p2[st] + p2[2*st] + sb;
            }
            sm[tid] = fmaxf(t1v[0], t1v[1]);
            __syncthreads();
            for (int s = 128; s > 0; s >>= 1) {
                if (tid < s) sm[tid] = fmaxf(sm[tid], sm[tid + s]);
                __syncthreads();
            }
            float M = sm[0];
            __syncthreads();
            float e0 = expf(t1v[0] - M), e1 = expf(t1v[1] - M);
            sm[tid] = e0 + e1;
            __syncthreads();
            for (int s = 128; s > 0; s >>= 1) {
                if (tid < s) sm[tid] += sm[tid + s];
                __syncthreads();
            }
            float inv = 1.f / sm[0];
            __syncthreads();
            float* cat = g_cat + (size_t)b * LZ + (size_t)l * Z_;
            cat[tid      ] = sigmoidf_(t2v[0]) * e0 * inv;
            cat[tid + 256] = sigmoidf_(t2v[1]) * e1 * inv;
        }
        gsync();

        // ===== single_li GEMM: 4 deterministic K-splits of 640 =====
        for (int w = blockIdx.x; w < 64; w += P) {
            const int ks = w / 16;
            const int r  = w - ks * 16;
            const int m0 = (r >> 3) * BM;
            const int n0 = (r & 7) * BN;
            const int koff = ks * 640;
            float acc[4][4] = {};
            gemm_tn_pass(g_cat + koff, LZ, Wsl + koff, LZ, 640, m0, n0, As, Bs, acc);
            float* o = g_hgp + (size_t)ks * B_ * H_;
            #pragma unroll
            for (int i = 0; i < 4; ++i)
                #pragma unroll
                for (int j = 0; j < 4; ++j)
                    o[(size_t)(m0 + (ty<<2) + i) * H_ + n0 + (tx<<2) + j] = acc[i][j];
        }
        gsync();

        // ===== reduce splits + bias -> h_g =====
        for (int idx = gtid; idx < B_*H_; idx += gthreads) {
            g_hg[idx] = bsl[idx % H_]
                      + g_hgp[idx] + g_hgp[B_*H_ + idx]
                      + g_hgp[2*B_*H_ + idx] + g_hgp[3*B_*H_ + idx];
        }
        gsync();
    }

    // ===== final y for t = T-1 =====
    for (int w = blockIdx.x; w < 16; w += P) {
        const int warp = tid >> 5, lane = tid & 31;
        const int b    = w * 8 + warp;
        const float* h  = g_hg + (size_t)b * H_;
        const float* wl = Wlin + (size_t)(T_-1) * H_;
        float s = 0.f;
        for (int k = lane; k < H_; k += 32) s = fmaf(h[k], wl[k], s);
        #pragma unroll
        for (int o2 = 16; o2 > 0; o2 >>= 1) s += __shfl_down_sync(0xffffffffu, s, o2);
        if (lane == 0) out[(size_t)(T_-1) * B_ + b] = s + blin[T_-1];
    }
}

// ---------------- host orchestration ---------------------------------------
extern "C" void kernel_launch(void* const* d_in, const int* in_sizes, int n_in,
                              void* d_out, int out_size)
{
    const float* x      = (const float*)d_in[0];
    const float* Wx     = (const float*)d_in[1];
    const float* Wh     = (const float*)d_in[2];
    const float* b_lstm = (const float*)d_in[3];
    const float* Wg_h   = (const float*)d_in[4];
    const float* Wg_p   = (const float*)d_in[5];
    const float* bg     = (const float*)d_in[6];
    const float* Wilc   = (const float*)d_in[7];
    const float* bilc   = (const float*)d_in[8];
    const float* Wsl    = (const float*)d_in[9];
    const float* bsl    = (const float*)d_in[10];
    const float* Wlin   = (const float*)d_in[11];
    const float* blin   = (const float*)d_in[12];
    float* out = (float*)d_out;

    // Safe co-resident grid size (recomputed every call; deterministic).
    int dev = 0;
    cudaGetDevice(&dev);
    int sms = 148;
    cudaDeviceGetAttribute(&sms, cudaDevAttrMultiProcessorCount, dev);
    int bpm = 1;
    cudaOccupancyMaxActiveBlocksPerMultiprocessor(&bpm, k_persist, 256, 0);
    if (bpm < 1) bpm = 1;
    if (bpm > 2) bpm = 2;
    int P = sms * bpm;

    k_persist<<<P, 256>>>(x, Wx, Wh, b_lstm, Wg_h, Wg_p, bg, Wilc, bilc,
                          Wsl, bsl, Wlin, blin, out);
}

// round 6
// speedup vs baseline: 1.3657x; 1.3657x over previous
#include <cuda_runtime.h>
#include <math.h>

#define T_ 64
#define B_ 128
#define H_ 512
#define A_ 3
#define L_ 5
#define Z_ 512
#define NH4 (4*H_)      /* 2048 */
#define N3Z (3*Z_)      /* 1536 */
#define LZ  (L_*Z_)     /* 2560 */

#define BM 64
#define BN 64
#define BK 16
#define ABNH4 (A_*B_*NH4)

// ---------------- persistent scratch (device globals; no allocation) -------
__device__ float g_hs[L_*A_*B_*H_];          // (l,a,b,h) hidden state
__device__ float g_cs[L_*A_*B_*H_];          // (l,a,b,h) cell state
__device__ float g_hg[B_*H_];                // h_g carry (B,H)
__device__ float g_prep[4*ABNH4];            // LSTM pre-activation K-split partials
__device__ float g_pre3[L_*A_*B_*N3Z];       // cell_fn pre (l,a,b,g*Z+z)
__device__ float g_icell[L_*A_*B_*Z_];
__device__ float g_ccell[L_*A_*B_*Z_];
__device__ float g_t1p[L_*A_*B_*Z_];         // per-(l,a) partials (deterministic)
__device__ float g_t2p[L_*A_*B_*Z_];
__device__ float g_hgp[4*B_*H_];             // single_li split-K partials
__device__ float g_cat[B_*LZ];

// ---------------- grid barrier ---------------------------------------------
__device__ unsigned g_cnt = 0;
__device__ volatile unsigned g_gen = 0;

__device__ __forceinline__ void gsync() {
    __syncthreads();
    if (threadIdx.x == 0) {
        unsigned gen = g_gen;
        __threadfence();
        if (atomicAdd(&g_cnt, 1u) == gridDim.x - 1) {
            g_cnt = 0;
            __threadfence();
            g_gen = gen + 1u;
        } else {
            while (g_gen == gen) { __nanosleep(32); }
        }
        __threadfence();
    }
    __syncthreads();
}

__device__ __forceinline__ float sigmoidf_(float x) { return 1.f / (1.f + expf(-x)); }

// ---------------- packed fp32x2 FMA helpers (sm_103a FFMA2) ----------------
__device__ __forceinline__ unsigned long long pk2(float lo, float hi) {
    unsigned long long r;
    asm("mov.b64 %0, {%1, %2};" : "=l"(r) : "f"(lo), "f"(hi));
    return r;
}
__device__ __forceinline__ void fma2_(unsigned long long& d,
                                      unsigned long long a, unsigned long long b) {
    asm("fma.rn.f32x2 %0, %1, %2, %0;" : "+l"(d) : "l"(a), "l"(b));
}
__device__ __forceinline__ float2 up2(unsigned long long v) {
    float2 f;
    asm("mov.b64 {%0, %1}, %2;" : "=f"(f.x), "=f"(f.y) : "l"(v));
    return f;
}

// ---------------- tiled GEMM core: TN, double-buffered, FFMA2 --------------
// acc(m0+i, n0+j pair) += A[m,:K] . B[n,:K]. K % 16 == 0, K/16 even.
// As/Bs: 2 buffers of BK*BM / BK*BN floats each.
__device__ __forceinline__ void gemm_tn_pass2(
    const float* __restrict__ Aop, int lda,
    const float* __restrict__ Bop, int ldb,
    int K, int m0, int n0,
    float* As, float* Bs, unsigned long long (&acc)[4][2])
{
    const int tid = threadIdx.x;
    const int tx = tid & 15, ty = tid >> 4;
    const int lr = tid >> 2;          // 0..63: tile row for loads
    const int lk = (tid & 3) << 2;    // 0,4,8,12: k offset for loads
    const float* Ap = Aop + (size_t)(m0 + lr) * lda + lk;
    const float* Bp = Bop + (size_t)(n0 + lr) * ldb + lk;
    float4 av = *(const float4*)(Ap);
    float4 bv = *(const float4*)(Bp);
    int buf = 0;
    for (int k0 = 0; k0 < K; k0 += BK) {
        float* Ab = As + buf * (BK*BM);
        float* Bb = Bs + buf * (BK*BN);
        Ab[(lk+0)*BM + lr] = av.x;
        Ab[(lk+1)*BM + lr] = av.y;
        Ab[(lk+2)*BM + lr] = av.z;
        Ab[(lk+3)*BM + lr] = av.w;
        Bb[(lk+0)*BN + lr] = bv.x;
        Bb[(lk+1)*BN + lr] = bv.y;
        Bb[(lk+2)*BN + lr] = bv.z;
        Bb[(lk+3)*BN + lr] = bv.w;
        __syncthreads();
        if (k0 + BK < K) {
            av = *(const float4*)(Ap + k0 + BK);
            bv = *(const float4*)(Bp + k0 + BK);
        }
        #pragma unroll
        for (int kk = 0; kk < BK; ++kk) {
            const float4 a4 = *(const float4*)(Ab + kk*BM + (ty<<2));
            const ulonglong2 b2 = *(const ulonglong2*)(Bb + kk*BN + (tx<<2));
            unsigned long long a0 = pk2(a4.x, a4.x);
            unsigned long long a1 = pk2(a4.y, a4.y);
            unsigned long long a2 = pk2(a4.z, a4.z);
            unsigned long long a3 = pk2(a4.w, a4.w);
            fma2_(acc[0][0], a0, b2.x); fma2_(acc[0][1], a0, b2.y);
            fma2_(acc[1][0], a1, b2.x); fma2_(acc[1][1], a1, b2.y);
            fma2_(acc[2][0], a2, b2.x); fma2_(acc[2][1], a2, b2.y);
            fma2_(acc[3][0], a3, b2.x); fma2_(acc[3][1], a3, b2.y);
        }
        buf ^= 1;
    }
}

__device__ __forceinline__ void store_tile(
    float* __restrict__ out, int ldo, int m0, int n0,
    unsigned long long (&acc)[4][2])
{
    const int tx = threadIdx.x & 15, ty = threadIdx.x >> 4;
    #pragma unroll
    for (int i = 0; i < 4; ++i) {
        float2 lo = up2(acc[i][0]);
        float2 hi = up2(acc[i][1]);
        *(float4*)(out + (size_t)(m0 + (ty<<2) + i) * ldo + n0 + (tx<<2))
            = make_float4(lo.x, lo.y, hi.x, hi.y);
    }
}

// ---------------- the single persistent kernel ------------------------------
__global__ __launch_bounds__(256, 2) void k_persist(
    const float* __restrict__ x,    const float* __restrict__ Wx,
    const float* __restrict__ Wh,   const float* __restrict__ b_lstm,
    const float* __restrict__ Wg_h, const float* __restrict__ Wg_p,
    const float* __restrict__ bg,   const float* __restrict__ Wilc,
    const float* __restrict__ bilc, const float* __restrict__ Wsl,
    const float* __restrict__ bsl,  const float* __restrict__ Wlin,
    const float* __restrict__ blin, float* __restrict__ out)
{
    __shared__ __align__(16) float sm[4096];   // 16 KB: 2x(As+Bs) or t12 bufs
    float* As = sm;                             // [2][BK*BM]
    float* Bs = sm + 2*BK*BM;                   // [2][BK*BN]

    const int P   = gridDim.x;
    const int tid = threadIdx.x;
    const int gthreads = P * 256;
    const int gtid = blockIdx.x * 256 + tid;

    // -------- init states --------
    for (int i = gtid; i < L_*A_*B_*H_; i += gthreads) { g_hs[i] = 0.f; g_cs[i] = 0.f; }
    for (int i = gtid; i < B_*H_; i += gthreads) g_hg[i] = 0.f;
    gsync();

    for (int t = 0; t < T_; ++t) {
        const float* xt = x + (size_t)t * B_ * H_;

        // ===== Multi-LSTM levels =====
        for (int l = 0; l < L_; ++l) {
            // --- GEMM stage: 768 quarter-K tiles (+16 y-items at l==0,t>0) ---
            const int extra = (l == 0 && t > 0) ? 16 : 0;
            for (int w = blockIdx.x; w < 768 + extra; w += P) {
                if (w < 768) {
                    const int ks = w / 192;          // K-split 0..3
                    const int r  = w - ks * 192;
                    const int a  = r >> 6;
                    const int rr = r & 63;
                    const int m0 = (rr >> 5) * BM;
                    const int n0 = (rr & 31) * BN;
                    const float* src;
                    const float* wsrc;
                    int koff;
                    if (ks < 2) {
                        src  = (l == 0) ? xt
                              : (g_hs + ((size_t)(l-1)*A_ + a) * B_ * H_);
                        wsrc = Wx + ((size_t)(a*L_ + l)) * 4 * H_ * H_;
                        koff = ks * 256;
                    } else {
                        src  = g_hs + ((size_t)l*A_ + a) * B_ * H_;
                        wsrc = Wh + ((size_t)(a*L_ + l)) * 4 * H_ * H_;
                        koff = (ks - 2) * 256;
                    }
                    unsigned long long acc[4][2] = {};
                    gemm_tn_pass2(src + koff, H_, wsrc + koff, H_, 256,
                                  m0, n0, As, Bs, acc);
                    store_tile(g_prep + (size_t)ks * ABNH4 + (size_t)a * B_ * NH4,
                               NH4, m0, n0, acc);
                } else {
                    // y for step t-1: item j covers batches 8j..8j+7
                    const int j    = w - 768;
                    const int warp = tid >> 5, lane = tid & 31;
                    const int b    = j * 8 + warp;
                    const float* h  = g_hg + (size_t)b * H_;
                    const float* wl = Wlin + (size_t)(t-1) * H_;
                    float s = 0.f;
                    for (int k = lane; k < H_; k += 32) s = fmaf(h[k], wl[k], s);
                    #pragma unroll
                    for (int o2 = 16; o2 > 0; o2 >>= 1)
                        s += __shfl_down_sync(0xffffffffu, s, o2);
                    if (lane == 0) out[(size_t)(t-1) * B_ + b] = s + blin[t-1];
                }
            }
            gsync();

            // --- pointwise gates: sum 4 K-split partials, in place hs/cs ---
            for (int idx = gtid; idx < A_*B_*H_; idx += gthreads) {
                int a = idx / (B_*H_);
                int r = idx - a * (B_*H_);
                int b = r / H_;
                int o = r - b * H_;
                size_t base = ((size_t)a * B_ + b) * NH4;
                const float* bb = b_lstm + ((size_t)(a*L_ + l)) * 4 * H_;
                float pi = bb[0*H_ + o], pf = bb[1*H_ + o];
                float pg = bb[2*H_ + o], po = bb[3*H_ + o];
                #pragma unroll
                for (int ks = 0; ks < 4; ++ks) {
                    const float* p = g_prep + (size_t)ks * ABNH4 + base;
                    pi += p[0*H_ + o];
                    pf += p[1*H_ + o];
                    pg += p[2*H_ + o];
                    po += p[3*H_ + o];
                }
                float ig = sigmoidf_(pi);
                float fg = sigmoidf_(pf);
                float gg = tanhf(pg);
                float og = sigmoidf_(po);
                size_t ci = ((size_t)(l*A_ + a) * B_ + b) * H_ + o;
                float c = fg * g_cs[ci] + ig * gg;
                g_cs[ci] = c;
                g_hs[ci] = og * tanhf(c);
            }
            gsync();
        }

        // ===== cell_fn pre GEMM: 720 tiles =====
        for (int w = blockIdx.x; w < 720; w += P) {
            const int la = w / 48;
            const int r  = w - la * 48;
            const int m0 = (r / 24) * BM;
            const int n0 = (r % 24) * BN;
            unsigned long long acc[4][2] = {};
            gemm_tn_pass2(g_hg, H_, Wg_h + (size_t)la * N3Z * H_, H_, H_,
                          m0, n0, As, Bs, acc);
            gemm_tn_pass2(g_hs + (size_t)la * B_ * H_, H_,
                          Wg_p + (size_t)la * N3Z * Z_, Z_, Z_,
                          m0, n0, As, Bs, acc);
            store_tile(g_pre3 + (size_t)la * B_ * N3Z, N3Z, m0, n0, acc);
        }
        gsync();

        // ===== cell_fn pointwise =====
        for (int idx = gtid; idx < L_*A_*B_*Z_; idx += gthreads) {
            int la = idx / (B_*Z_);
            int r  = idx - la * (B_*Z_);
            int z  = r % Z_;
            size_t base = ((size_t)la * B_ + (r / Z_)) * N3Z;
            const float* bb = bg + (size_t)la * N3Z;
            float ig = sigmoidf_(g_pre3[base + 0*Z_ + z] + bb[0*Z_ + z]);
            float fg = sigmoidf_(g_pre3[base + 1*Z_ + z] + bb[1*Z_ + z]);
            float gg = tanhf    (g_pre3[base + 2*Z_ + z] + bb[2*Z_ + z]);
            float ic = ig * g_cs[idx];              // sc: identical (l,a,b,h) layout
            g_icell[idx] = ic;
            g_ccell[idx] = fg * gg + ic;
        }
        gsync();

        // ===== t1/t2 GEMM per (l,a): 240 tiles, deterministic partials =====
        for (int w = blockIdx.x; w < 240; w += P) {
            const int la = w / 16;
            const int r  = w - la * 16;
            const int m0 = (r >> 3) * BM;
            const int n0 = (r & 7) * BN;
            const float* A1 = g_icell + (size_t)la * B_ * Z_;
            const float* A2 = g_ccell + (size_t)la * B_ * Z_;
            const float* W  = Wilc    + (size_t)la * Z_ * Z_;
            float* As1 = sm; float* As2 = sm + BK*BM; float* Bs2 = sm + 2*BK*BM;
            unsigned long long acc1[4][2] = {}, acc2[4][2] = {};
            const int tx = tid & 15, ty = tid >> 4;
            const int lr  = tid >> 2, lk = (tid & 3) << 2;   // A loaders (transpose)
            const int bkr = tid >> 4, bnc = (tid & 15) << 2; // B loader (K-major direct)
            for (int k0 = 0; k0 < Z_; k0 += BK) {
                float4 a1 = *(const float4*)(A1 + (size_t)(m0 + lr) * Z_ + k0 + lk);
                float4 a2 = *(const float4*)(A2 + (size_t)(m0 + lr) * Z_ + k0 + lk);
                As1[(lk+0)*BM + lr] = a1.x; As1[(lk+1)*BM + lr] = a1.y;
                As1[(lk+2)*BM + lr] = a1.z; As1[(lk+3)*BM + lr] = a1.w;
                As2[(lk+0)*BM + lr] = a2.x; As2[(lk+1)*BM + lr] = a2.y;
                As2[(lk+2)*BM + lr] = a2.z; As2[(lk+3)*BM + lr] = a2.w;
                float4 bv = *(const float4*)(W + (size_t)(k0 + bkr) * Z_ + n0 + bnc);
                *(float4*)(Bs2 + bkr*BN + bnc) = bv;
                __syncthreads();
                #pragma unroll
                for (int kk = 0; kk < BK; ++kk) {
                    const float4 a14 = *(const float4*)(As1 + kk*BM + (ty<<2));
                    const float4 a24 = *(const float4*)(As2 + kk*BM + (ty<<2));
                    const ulonglong2 b2 = *(const ulonglong2*)(Bs2 + kk*BN + (tx<<2));
                    unsigned long long u0 = pk2(a14.x, a14.x), u1 = pk2(a14.y, a14.y);
                    unsigned long long u2 = pk2(a14.z, a14.z), u3 = pk2(a14.w, a14.w);
                    unsigned long long v0 = pk2(a24.x, a24.x), v1 = pk2(a24.y, a24.y);
                    unsigned long long v2 = pk2(a24.z, a24.z), v3 = pk2(a24.w, a24.w);
                    fma2_(acc1[0][0], u0, b2.x); fma2_(acc1[0][1], u0, b2.y);
                    fma2_(acc1[1][0], u1, b2.x); fma2_(acc1[1][1], u1, b2.y);
                    fma2_(acc1[2][0], u2, b2.x); fma2_(acc1[2][1], u2, b2.y);
                    fma2_(acc1[3][0], u3, b2.x); fma2_(acc1[3][1], u3, b2.y);
                    fma2_(acc2[0][0], v0, b2.x); fma2_(acc2[0][1], v0, b2.y);
                    fma2_(acc2[1][0], v1, b2.x); fma2_(acc2[1][1], v1, b2.y);
                    fma2_(acc2[2][0], v2, b2.x); fma2_(acc2[2][1], v2, b2.y);
                    fma2_(acc2[3][0], v3, b2.x); fma2_(acc2[3][1], v3, b2.y);
                }
                __syncthreads();
            }
            store_tile(g_t1p + (size_t)la * B_ * Z_, Z_, m0, n0, acc1);
            store_tile(g_t2p + (size_t)la * B_ * Z_, Z_, m0, n0, acc2);
        }
        gsync();

        // ===== combine: axis-sum + bias, sigmoid(t2)*softmax(t1) -> cat =====
        for (int row = blockIdx.x; row < L_*B_; row += P) {
            const int l = row / B_, b = row % B_;
            float t1v[2], t2v[2];
            #pragma unroll
            for (int h = 0; h < 2; ++h) {
                const int y = tid + h*256;
                float sb = bilc[(size_t)(l*A_+0)*Z_ + y]
                         + bilc[(size_t)(l*A_+1)*Z_ + y]
                         + bilc[(size_t)(l*A_+2)*Z_ + y];
                size_t off = (size_t)b * Z_ + y;
                size_t st  = (size_t)B_ * Z_;
                const float* p1 = g_t1p + (size_t)(l*A_) * st + off;
                const float* p2 = g_t2p + (size_t)(l*A_) * st + off;
                t1v[h] = p1[0] + p1[st] + p1[2*st] + sb;
                t2v[h] = p2[0] + p2[st] + p2[2*st] + sb;
            }
            sm[tid] = fmaxf(t1v[0], t1v[1]);
            __syncthreads();
            for (int s = 128; s > 0; s >>= 1) {
                if (tid < s) sm[tid] = fmaxf(sm[tid], sm[tid + s]);
                __syncthreads();
            }
            float M = sm[0];
            __syncthreads();
            float e0 = expf(t1v[0] - M), e1 = expf(t1v[1] - M);
            sm[tid] = e0 + e1;
            __syncthreads();
            for (int s = 128; s > 0; s >>= 1) {
                if (tid < s) sm[tid] += sm[tid + s];
                __syncthreads();
            }
            float inv = 1.f / sm[0];
            __syncthreads();
            float* cat = g_cat + (size_t)b * LZ + (size_t)l * Z_;
            cat[tid      ] = sigmoidf_(t2v[0]) * e0 * inv;
            cat[tid + 256] = sigmoidf_(t2v[1]) * e1 * inv;
        }
        gsync();

        // ===== single_li GEMM: 4 deterministic K-splits of 640 =====
        for (int w = blockIdx.x; w < 64; w += P) {
            const int ks = w / 16;
            const int r  = w - ks * 16;
            const int m0 = (r >> 3) * BM;
            const int n0 = (r & 7) * BN;
            const int koff = ks * 640;
            unsigned long long acc[4][2] = {};
            gemm_tn_pass2(g_cat + koff, LZ, Wsl + koff, LZ, 640, m0, n0, As, Bs, acc);
            store_tile(g_hgp + (size_t)ks * B_ * H_, H_, m0, n0, acc);
        }
        gsync();

        // ===== reduce splits + bias -> h_g =====
        for (int idx = gtid; idx < B_*H_; idx += gthreads) {
            g_hg[idx] = bsl[idx % H_]
                      + g_hgp[idx] + g_hgp[B_*H_ + idx]
                      + g_hgp[2*B_*H_ + idx] + g_hgp[3*B_*H_ + idx];
        }
        gsync();
    }

    // ===== final y for t = T-1 =====
    for (int w = blockIdx.x; w < 16; w += P) {
        const int warp = tid >> 5, lane = tid & 31;
        const int b    = w * 8 + warp;
        const float* h  = g_hg + (size_t)b * H_;
        const float* wl = Wlin + (size_t)(T_-1) * H_;
        float s = 0.f;
        for (int k = lane; k < H_; k += 32) s = fmaf(h[k], wl[k], s);
        #pragma unroll
        for (int o2 = 16; o2 > 0; o2 >>= 1) s += __shfl_down_sync(0xffffffffu, s, o2);
        if (lane == 0) out[(size_t)(T_-1) * B_ + b] = s + blin[T_-1];
    }
}

// ---------------- host orchestration ---------------------------------------
extern "C" void kernel_launch(void* const* d_in, const int* in_sizes, int n_in,
                              void* d_out, int out_size)
{
    const float* x      = (const float*)d_in[0];
    const float* Wx     = (const float*)d_in[1];
    const float* Wh     = (const float*)d_in[2];
    const float* b_lstm = (const float*)d_in[3];
    const float* Wg_h   = (const float*)d_in[4];
    const float* Wg_p   = (const float*)d_in[5];
    const float* bg     = (const float*)d_in[6];
    const float* Wilc   = (const float*)d_in[7];
    const float* bilc   = (const float*)d_in[8];
    const float* Wsl    = (const float*)d_in[9];
    const float* bsl    = (const float*)d_in[10];
    const float* Wlin   = (const float*)d_in[11];
    const float* blin   = (const float*)d_in[12];
    float* out = (float*)d_out;

    // Safe co-resident grid size (recomputed every call; deterministic).
    int dev = 0;
    cudaGetDevice(&dev);
    int sms = 148;
    cudaDeviceGetAttribute(&sms, cudaDevAttrMultiProcessorCount, dev);
    int bpm = 1;
    cudaOccupancyMaxActiveBlocksPerMultiprocessor(&bpm, k_persist, 256, 0);
    if (bpm < 1) bpm = 1;
    if (bpm > 2) bpm = 2;
    int P = sms * bpm;

    k_persist<<<P, 256>>>(x, Wx, Wh, b_lstm, Wg_h, Wg_p, bg, Wilc, bilc,
                          Wsl, bsl, Wlin, blin, out);
}

// round 8
// speedup vs baseline: 1.6267x; 1.1911x over previous
#include <cuda_runtime.h>
#include <math.h>

#define T_ 64
#define B_ 128
#define H_ 512
#define A_ 3
#define L_ 5
#define Z_ 512
#define NH4 (4*H_)      /* 2048 */
#define N3Z (3*Z_)      /* 1536 */
#define LZ  (L_*Z_)     /* 2560 */

#define BK 16
#define ABNH4 (A_*B_*NH4)
#define LABZ (L_*A_*B_*Z_)

typedef unsigned long long u64;

// ---------------- persistent scratch (device globals; no allocation) -------
__device__ float g_hs[L_*A_*B_*H_];          // (l,a,b,h) hidden state
__device__ float g_cs[L_*A_*B_*H_];          // (l,a,b,h) cell state
__device__ float g_hg[B_*H_];                // h_g carry (B,H)
__device__ float g_prep[6*ABNH4];            // LSTM pre-activation K-split partials
__device__ float g_pre3[6*L_*A_*B_*N3Z];     // cell_fn pre K-split partials
__device__ float g_icell[LABZ];
__device__ float g_ccell[LABZ];
__device__ float g_t1p[2*LABZ];              // t1 partials (2 K-splits)
__device__ float g_t2p[2*LABZ];
__device__ float g_hgp[10*B_*H_];            // single_li split-K partials
__device__ float g_cat[B_*LZ];

// ---------------- grid barrier ---------------------------------------------
__device__ unsigned g_cnt = 0;
__device__ volatile unsigned g_gen = 0;

__device__ __forceinline__ void gsync() {
    __syncthreads();
    if (threadIdx.x == 0) {
        unsigned gen = g_gen;
        __threadfence();
        if (atomicAdd(&g_cnt, 1u) == gridDim.x - 1) {
            g_cnt = 0;
            __threadfence();
            g_gen = gen + 1u;
        } else {
            while (g_gen == gen) { __nanosleep(32); }
        }
        __threadfence();
    }
    __syncthreads();
}

__device__ __forceinline__ float sigmoidf_(float x) { return 1.f / (1.f + expf(-x)); }

// ---------------- packed fp32x2 FMA helpers (sm_103a FFMA2) ----------------
__device__ __forceinline__ u64 pk2(float lo, float hi) {
    u64 r;
    asm("mov.b64 %0, {%1, %2};" : "=l"(r) : "f"(lo), "f"(hi));
    return r;
}
__device__ __forceinline__ void fma2_(u64& d, u64 a, u64 b) {
    asm("fma.rn.f32x2 %0, %1, %2, %0;" : "+l"(d) : "l"(a), "l"(b));
}
__device__ __forceinline__ float2 up2(u64 v) {
    float2 f;
    asm("mov.b64 {%0, %1}, %2;" : "=f"(f.x), "=f"(f.y) : "l"(v));
    return f;
}

// ---------------- 128x128 tiled GEMM core, 8x8 microtile, FFMA2 ------------
// M = 128 fixed (full batch). acc += A[0..127,:K] . B[n0+j,:K].
// b_kmajor=0: B rows are N (K-contiguous, TN). b_kmajor=1: B rows are K
// (N-contiguous, NN — used for Wilc). K % 16 == 0. 256 threads.
__device__ __forceinline__ void gemm128(
    const float* __restrict__ Aop, int lda,
    const float* __restrict__ Bop, int ldb, int b_kmajor,
    int K, int n0, float* As, float* Bs, u64 (&acc)[8][4])
{
    const int tid = threadIdx.x;
    const int tx = tid & 15, ty = tid >> 4;
    const int lr = tid >> 1, lk = (tid & 1) << 3;   // transpose loaders
    const int kr = tid >> 4, nc = (tid & 15) << 3;  // NN direct loader
    const float* Ap = Aop + (size_t)lr * lda + lk;
    const float* Bp = b_kmajor ? (Bop + (size_t)kr * ldb + n0 + nc)
                               : (Bop + (size_t)(n0 + lr) * ldb + lk);
    float4 av0 = *(const float4*)(Ap);
    float4 av1 = *(const float4*)(Ap + 4);
    float4 bv0 = *(const float4*)(Bp);
    float4 bv1 = *(const float4*)(Bp + 4);
    int buf = 0;
    for (int k0 = 0; k0 < K; k0 += BK) {
        float* Ab = As + buf * (BK*128);
        float* Bb = Bs + buf * (BK*128);
        Ab[(lk+0)*128 + lr] = av0.x;
        Ab[(lk+1)*128 + lr] = av0.y;
        Ab[(lk+2)*128 + lr] = av0.z;
        Ab[(lk+3)*128 + lr] = av0.w;
        Ab[(lk+4)*128 + lr] = av1.x;
        Ab[(lk+5)*128 + lr] = av1.y;
        Ab[(lk+6)*128 + lr] = av1.z;
        Ab[(lk+7)*128 + lr] = av1.w;
        if (b_kmajor) {
            *(float4*)(Bb + kr*128 + nc)     = bv0;
            *(float4*)(Bb + kr*128 + nc + 4) = bv1;
        } else {
            Bb[(lk+0)*128 + lr] = bv0.x;
            Bb[(lk+1)*128 + lr] = bv0.y;
            Bb[(lk+2)*128 + lr] = bv0.z;
            Bb[(lk+3)*128 + lr] = bv0.w;
            Bb[(lk+4)*128 + lr] = bv1.x;
            Bb[(lk+5)*128 + lr] = bv1.y;
            Bb[(lk+6)*128 + lr] = bv1.z;
            Bb[(lk+7)*128 + lr] = bv1.w;
        }
        __syncthreads();
        if (k0 + BK < K) {
            av0 = *(const float4*)(Ap + k0 + BK);
            av1 = *(const float4*)(Ap + k0 + BK + 4);
            if (b_kmajor) {
                bv0 = *(const float4*)(Bp + (size_t)(k0 + BK) * ldb);
                bv1 = *(const float4*)(Bp + (size_t)(k0 + BK) * ldb + 4);
            } else {
                bv0 = *(const float4*)(Bp + k0 + BK);
                bv1 = *(const float4*)(Bp + k0 + BK + 4);
            }
        }
        #pragma unroll
        for (int kk = 0; kk < BK; ++kk) {
            const float4 a0 = *(const float4*)(Ab + kk*128 + (ty<<3));
            const float4 a1 = *(const float4*)(Ab + kk*128 + (ty<<3) + 4);
            const ulonglong2 b0 = *(const ulonglong2*)(Bb + kk*128 + (tx<<3));
            const ulonglong2 b1 = *(const ulonglong2*)(Bb + kk*128 + (tx<<3) + 4);
            float am[8] = {a0.x,a0.y,a0.z,a0.w,a1.x,a1.y,a1.z,a1.w};
            #pragma unroll
            for (int i = 0; i < 8; ++i) {
                u64 ai = pk2(am[i], am[i]);
                fma2_(acc[i][0], ai, b0.x);
                fma2_(acc[i][1], ai, b0.y);
                fma2_(acc[i][2], ai, b1.x);
                fma2_(acc[i][3], ai, b1.y);
            }
        }
        buf ^= 1;
    }
}

__device__ __forceinline__ void store_tile128(
    float* __restrict__ out, int ldo, int n0, u64 (&acc)[8][4])
{
    const int tx = threadIdx.x & 15, ty = threadIdx.x >> 4;
    #pragma unroll
    for (int i = 0; i < 8; ++i) {
        float2 p0 = up2(acc[i][0]), p1 = up2(acc[i][1]);
        float2 p2 = up2(acc[i][2]), p3 = up2(acc[i][3]);
        float* row = out + (size_t)((ty<<3) + i) * ldo + n0 + (tx<<3);
        *(float4*)(row)     = make_float4(p0.x, p0.y, p1.x, p1.y);
        *(float4*)(row + 4) = make_float4(p2.x, p2.y, p3.x, p3.y);
    }
}

// K chunk table for 512 -> 3 chunks (all multiples of BK)
__device__ __constant__ int c_ko[3] = {0, 176, 352};
__device__ __constant__ int c_kc[3] = {176, 176, 160};

// ---------------- the single persistent kernel ------------------------------
__global__ __launch_bounds__(256, 2) void k_persist(
    const float* __restrict__ x,    const float* __restrict__ Wx,
    const float* __restrict__ Wh,   const float* __restrict__ b_lstm,
    const float* __restrict__ Wg_h, const float* __restrict__ Wg_p,
    const float* __restrict__ bg,   const float* __restrict__ Wilc,
    const float* __restrict__ bilc, const float* __restrict__ Wsl,
    const float* __restrict__ bsl,  const float* __restrict__ Wlin,
    const float* __restrict__ blin, float* __restrict__ out)
{
    __shared__ __align__(16) float sm[2*BK*128 + 2*BK*128];  // 32 KB
    float* As = sm;                  // [2][BK*128]
    float* Bs = sm + 2*BK*128;       // [2][BK*128]

    const int P   = gridDim.x;
    const int tid = threadIdx.x;
    const int gthreads = P * 256;
    const int gtid = blockIdx.x * 256 + tid;

    // -------- init states --------
    for (int i = gtid; i < L_*A_*B_*H_; i += gthreads) { g_hs[i] = 0.f; g_cs[i] = 0.f; }
    for (int i = gtid; i < B_*H_; i += gthreads) g_hg[i] = 0.f;
    gsync();

    for (int t = 0; t < T_; ++t) {
        const float* xt = x + (size_t)t * B_ * H_;

        // ===== Multi-LSTM levels =====
        for (int l = 0; l < L_; ++l) {
            // --- GEMM stage: 288 items (+16 y-items at l==0, t>0) ---
            const int extra = (l == 0 && t > 0) ? 16 : 0;
            for (int w = blockIdx.x; w < 288 + extra; w += P) {
                if (w < 288) {
                    const int ks = w / 48;           // 0..5
                    const int r  = w - ks * 48;
                    const int a  = r >> 4;           // 0..2
                    const int n0 = (r & 15) << 7;    // 0..15 * 128
                    const int cc = (ks < 3) ? ks : (ks - 3);
                    const int ko = c_ko[cc], kc = c_kc[cc];
                    const float* src;
                    const float* wsrc;
                    if (ks < 3) {
                        src  = (l == 0) ? xt
                              : (g_hs + ((size_t)(l-1)*A_ + a) * B_ * H_);
                        wsrc = Wx + ((size_t)(a*L_ + l)) * 4 * H_ * H_;
                    } else {
                        src  = g_hs + ((size_t)l*A_ + a) * B_ * H_;
                        wsrc = Wh + ((size_t)(a*L_ + l)) * 4 * H_ * H_;
                    }
                    u64 acc[8][4] = {};
                    gemm128(src + ko, H_, wsrc + ko, H_, 0, kc, n0, As, Bs, acc);
                    store_tile128(g_prep + (size_t)ks * ABNH4 + (size_t)a * B_ * NH4,
                                  NH4, n0, acc);
                } else {
                    // y for step t-1: item j covers batches 8j..8j+7
                    const int j    = w - 288;
                    const int warp = tid >> 5, lane = tid & 31;
                    const int b    = j * 8 + warp;
                    const float* h  = g_hg + (size_t)b * H_;
                    const float* wl = Wlin + (size_t)(t-1) * H_;
                    float s = 0.f;
                    for (int k = lane; k < H_; k += 32) s = fmaf(h[k], wl[k], s);
                    #pragma unroll
                    for (int o2 = 16; o2 > 0; o2 >>= 1)
                        s += __shfl_down_sync(0xffffffffu, s, o2);
                    if (lane == 0) out[(size_t)(t-1) * B_ + b] = s + blin[t-1];
                }
            }
            gsync();

            // --- pointwise gates: sum 6 K-split partials, in place hs/cs ---
            for (int idx = gtid; idx < A_*B_*H_; idx += gthreads) {
                int a = idx / (B_*H_);
                int r = idx - a * (B_*H_);
                int b = r / H_;
                int o = r - b * H_;
                size_t base = ((size_t)a * B_ + b) * NH4;
                const float* bb = b_lstm + ((size_t)(a*L_ + l)) * 4 * H_;
                float pi = bb[0*H_ + o], pf = bb[1*H_ + o];
                float pg = bb[2*H_ + o], po = bb[3*H_ + o];
                #pragma unroll
                for (int ks = 0; ks < 6; ++ks) {
                    const float* p = g_prep + (size_t)ks * ABNH4 + base;
                    pi += p[0*H_ + o];
                    pf += p[1*H_ + o];
                    pg += p[2*H_ + o];
                    po += p[3*H_ + o];
                }
                float ig = sigmoidf_(pi);
                float fg = sigmoidf_(pf);
                float gg = tanhf(pg);
                float og = sigmoidf_(po);
                size_t ci = ((size_t)(l*A_ + a) * B_ + b) * H_ + o;
                float c = fg * g_cs[ci] + ig * gg;
                g_cs[ci] = c;
                g_hs[ci] = og * tanhf(c);
            }
            gsync();
        }

        // ===== cell_fn pre GEMM: 1080 items (15 la x 12 ntiles x 6 ks) =====
        for (int w = blockIdx.x; w < 1080; w += P) {
            const int la = w / 72;
            const int r  = w - la * 72;
            const int ks = r / 12;
            const int n0 = (r % 12) << 7;
            const int cc = (ks < 3) ? ks : (ks - 3);
            const int ko = c_ko[cc], kc = c_kc[cc];
            const float* src;
            const float* wsrc;
            if (ks < 3) {
                src  = g_hg;
                wsrc = Wg_h + (size_t)la * N3Z * H_;
            } else {
                src  = g_hs + (size_t)la * B_ * H_;
                wsrc = Wg_p + (size_t)la * N3Z * Z_;
            }
            u64 acc[8][4] = {};
            gemm128(src + ko, H_, wsrc + ko, H_, 0, kc, n0, As, Bs, acc);
            store_tile128(g_pre3 + (size_t)ks * (L_*A_*B_*N3Z)
                                 + (size_t)la * B_ * N3Z, N3Z, n0, acc);
        }
        gsync();

        // ===== cell_fn pointwise: sum 6 partials =====
        for (int idx = gtid; idx < LABZ; idx += gthreads) {
            int la = idx / (B_*Z_);
            int r  = idx - la * (B_*Z_);
            int z  = r % Z_;
            size_t base = ((size_t)la * B_ + (r / Z_)) * N3Z;
            const float* bb = bg + (size_t)la * N3Z;
            float vi = bb[0*Z_ + z], vf = bb[1*Z_ + z], vg = bb[2*Z_ + z];
            #pragma unroll
            for (int ks = 0; ks < 6; ++ks) {
                const float* p = g_pre3 + (size_t)ks * (L_*A_*B_*N3Z) + base;
                vi += p[0*Z_ + z];
                vf += p[1*Z_ + z];
                vg += p[2*Z_ + z];
            }
            float ig = sigmoidf_(vi);
            float fg = sigmoidf_(vf);
            float gg = tanhf(vg);
            float ic = ig * g_cs[idx];              // sc: identical (l,a,b,h) layout
            g_icell[idx] = ic;
            g_ccell[idx] = fg * gg + ic;
        }
        gsync();

        // ===== t1/t2 GEMM: 240 items (15 la x {t1,t2} x 2 ks x 4 ntiles) ====
        for (int w = blockIdx.x; w < 240; w += P) {
            const int la = w / 16;
            const int r  = w - la * 16;
            const int which = r >> 3;               // 0 = t1 (icell), 1 = t2
            const int rr = r & 7;
            const int ks = rr >> 2;                 // K chunk 0/1 (256 each)
            const int n0 = (rr & 3) << 7;
            const float* Aop = (which ? g_ccell : g_icell)
                               + (size_t)la * B_ * Z_ + ks * 256;
            const float* W = Wilc + (size_t)la * Z_ * Z_ + (size_t)(ks * 256) * Z_;
            u64 acc[8][4] = {};
            gemm128(Aop, Z_, W, Z_, 1, 256, n0, As, Bs, acc);
            float* dst = (which ? g_t2p : g_t1p)
                         + (size_t)ks * LABZ + (size_t)la * B_ * Z_;
            store_tile128(dst, Z_, n0, acc);
        }
        gsync();

        // ===== combine: sum axes+ks, sigmoid(t2)*softmax(t1) -> cat =====
        for (int row = blockIdx.x; row < L_*B_; row += P) {
            const int l = row / B_, b = row % B_;
            float t1v[2], t2v[2];
            #pragma unroll
            for (int h = 0; h < 2; ++h) {
                const int y = tid + h*256;
                float sb = bilc[(size_t)(l*A_+0)*Z_ + y]
                         + bilc[(size_t)(l*A_+1)*Z_ + y]
                         + bilc[(size_t)(l*A_+2)*Z_ + y];
                size_t off = (size_t)(l*A_) * B_ * Z_ + (size_t)b * Z_ + y;
                size_t st  = (size_t)B_ * Z_;
                const float* p1 = g_t1p + off;
                const float* p2 = g_t2p + off;
                t1v[h] = p1[0] + p1[st] + p1[2*st]
                       + p1[LABZ] + p1[LABZ+st] + p1[LABZ+2*st] + sb;
                t2v[h] = p2[0] + p2[st] + p2[2*st]
                       + p2[LABZ] + p2[LABZ+st] + p2[LABZ+2*st] + sb;
            }
            sm[tid] = fmaxf(t1v[0], t1v[1]);
            __syncthreads();
            for (int s = 128; s > 0; s >>= 1) {
                if (tid < s) sm[tid] = fmaxf(sm[tid], sm[tid + s]);
                __syncthreads();
            }
            float M = sm[0];
            __syncthreads();
            float e0 = expf(t1v[0] - M), e1 = expf(t1v[1] - M);
            sm[tid] = e0 + e1;
            __syncthreads();
            for (int s = 128; s > 0; s >>= 1) {
                if (tid < s) sm[tid] += sm[tid + s];
                __syncthreads();
            }
            float inv = 1.f / sm[0];
            __syncthreads();
            float* cat = g_cat + (size_t)b * LZ + (size_t)l * Z_;
            cat[tid      ] = sigmoidf_(t2v[0]) * e0 * inv;
            cat[tid + 256] = sigmoidf_(t2v[1]) * e1 * inv;
        }
        gsync();

        // ===== single_li GEMM: 40 items (10 K-chunks x 4 ntiles) =====
        for (int w = blockIdx.x; w < 40; w += P) {
            const int ks = w >> 2;
            const int n0 = (w & 3) << 7;
            const int koff = ks * 256;
            u64 acc[8][4] = {};
            gemm128(g_cat + koff, LZ, Wsl + koff, LZ, 0, 256, n0, As, Bs, acc);
            store_tile128(g_hgp + (size_t)ks * B_ * H_, H_, n0, acc);
        }
        gsync();

        // ===== reduce 10 splits + bias -> h_g =====
        for (int idx = gtid; idx < B_*H_; idx += gthreads) {
            float s = bsl[idx % H_];
            #pragma unroll
            for (int ks = 0; ks < 10; ++ks) s += g_hgp[(size_t)ks * B_ * H_ + idx];
            g_hg[idx] = s;
        }
        gsync();
    }

    // ===== final y for t = T-1 =====
    for (int w = blockIdx.x; w < 16; w += P) {
        const int warp = tid >> 5, lane = tid & 31;
        const int b    = w * 8 + warp;
        const float* h  = g_hg + (size_t)b * H_;
        const float* wl = Wlin + (size_t)(T_-1) * H_;
        float s = 0.f;
        for (int k = lane; k < H_; k += 32) s = fmaf(h[k], wl[k], s);
        #pragma unroll
        for (int o2 = 16; o2 > 0; o2 >>= 1) s += __shfl_down_sync(0xffffffffu, s, o2);
        if (lane == 0) out[(size_t)(T_-1) * B_ + b] = s + blin[T_-1];
    }
}

// ---------------- host orchestration ---------------------------------------
extern "C" void kernel_launch(void* const* d_in, const int* in_sizes, int n_in,
                              void* d_out, int out_size)
{
    const float* x      = (const float*)d_in[0];
    const float* Wx     = (const float*)d_in[1];
    const float* Wh     = (const float*)d_in[2];
    const float* b_lstm = (const float*)d_in[3];
    const float* Wg_h   = (const float*)d_in[4];
    const float* Wg_p   = (const float*)d_in[5];
    const float* bg     = (const float*)d_in[6];
    const float* Wilc   = (const float*)d_in[7];
    const float* bilc   = (const float*)d_in[8];
    const float* Wsl    = (const float*)d_in[9];
    const float* bsl    = (const float*)d_in[10];
    const float* Wlin   = (const float*)d_in[11];
    const float* blin   = (const float*)d_in[12];
    float* out = (float*)d_out;

    // Safe co-resident grid size (recomputed every call; deterministic).
    int dev = 0;
    cudaGetDevice(&dev);
    int sms = 148;
    cudaDeviceGetAttribute(&sms, cudaDevAttrMultiProcessorCount, dev);
    int bpm = 1;
    cudaOccupancyMaxActiveBlocksPerMultiprocessor(&bpm, k_persist, 256, 0);
    if (bpm < 1) bpm = 1;
    if (bpm > 2) bpm = 2;
    int P = sms * bpm;

    k_persist<<<P, 256>>>(x, Wx, Wh, b_lstm, Wg_h, Wg_p, bg, Wilc, bilc,
                          Wsl, bsl, Wlin, blin, out);
}

// round 12
// speedup vs baseline: 1.7787x; 1.0934x over previous
#include <cuda_runtime.h>
#include <cuda_bf16.h>
#include <math.h>
#include <stdint.h>

#define T_ 64
#define B_ 128
#define H_ 512
#define A_ 3
#define L_ 5
#define Z_ 512
#define NH4 (4*H_)      /* 2048 */
#define N3Z (3*Z_)      /* 1536 */
#define LZ  (L_*Z_)     /* 2560 */

#define ABNH4  (A_*B_*NH4)
#define LABZ   (L_*A_*B_*Z_)
#define LABN3Z (L_*A_*B_*N3Z)

#define NWX   (A_*L_*4*H_*H_)      /* 15728640 */
#define NWG   (L_*A_*3*Z_*H_)      /* 11796480 */
#define NWILC (L_*A_*Z_*Z_)        /* 3932160  */
#define NWSL  (H_*LZ)              /* 1310720  */

#define KC   32                     /* K chunk staged in smem */
#define APAD 8
#define ASTR (KC + APAD)            /* 40 elems = 80 B row stride */

// ---------------- persistent scratch (device globals; no allocation) -------
__device__ float g_hs[L_*A_*B_*H_];
__device__ float g_cs[L_*A_*B_*H_];
__device__ float g_hg[B_*H_];
__device__ float g_prep[6*ABNH4];
__device__ float g_pre3[6*LABN3Z];
__device__ float g_icell[LABZ];
__device__ float g_ccell[LABZ];
__device__ float g_t1p[2*LABZ];
__device__ float g_t2p[2*LABZ];
__device__ float g_hgp[10*B_*H_];
__device__ float g_cat[B_*LZ];

// pre-split bf16 weights (hi/lo), converted once per launch
__device__ __nv_bfloat16 cWx_h[NWX],   cWx_l[NWX];
__device__ __nv_bfloat16 cWh_h[NWX],   cWh_l[NWX];
__device__ __nv_bfloat16 cWgh_h[NWG],  cWgh_l[NWG];
__device__ __nv_bfloat16 cWgp_h[NWG],  cWgp_l[NWG];
__device__ __nv_bfloat16 cWilc_h[NWILC], cWilc_l[NWILC];   // TRANSPOSED [la][y][z]
__device__ __nv_bfloat16 cWsl_h[NWSL], cWsl_l[NWSL];

// ---------------- grid barrier ---------------------------------------------
__device__ unsigned g_cnt = 0;
__device__ volatile unsigned g_gen = 0;

__device__ __forceinline__ void gsync() {
    __syncthreads();
    if (threadIdx.x == 0) {
        unsigned gen = g_gen;
        __threadfence();
        if (atomicAdd(&g_cnt, 1u) == gridDim.x - 1) {
            g_cnt = 0;
            __threadfence();
            g_gen = gen + 1u;
        } else {
            while (g_gen == gen) { __nanosleep(32); }
        }
        __threadfence();
    }
    __syncthreads();
}

__device__ __forceinline__ float sigmoidf_(float x) { return 1.f / (1.f + expf(-x)); }

__device__ __forceinline__ void cvt_split(float x, __nv_bfloat16& h, __nv_bfloat16& l) {
    h = __float2bfloat16_rn(x);
    l = __float2bfloat16_rn(x - __bfloat162float(h));
}

__device__ __forceinline__ uint32_t smem_u32(const void* p) {
    uint32_t a;
    asm("{ .reg .u64 t; cvta.to.shared.u64 t, %1; cvt.u32.u64 %0, t; }"
        : "=r"(a) : "l"(p));
    return a;
}

// ---------------- baseline (non-'a') tensor ops: ldmatrix + mma.sync -------
__device__ __forceinline__ void ldm4(uint32_t* r, uint32_t addr) {
    asm volatile("ldmatrix.sync.aligned.m8n8.x4.shared.b16 {%0,%1,%2,%3}, [%4];"
        : "=r"(r[0]), "=r"(r[1]), "=r"(r[2]), "=r"(r[3]) : "r"(addr));
}
__device__ __forceinline__ void mma_bf16(float* c, const uint32_t* a,
                                         const uint32_t* b) {
    asm volatile(
        "mma.sync.aligned.m16n8k16.row.col.f32.bf16.bf16.f32 "
        "{%0,%1,%2,%3}, {%4,%5,%6,%7}, {%8,%9}, {%0,%1,%2,%3};"
        : "+f"(c[0]), "+f"(c[1]), "+f"(c[2]), "+f"(c[3])
        : "r"(a[0]), "r"(a[1]), "r"(a[2]), "r"(a[3]), "r"(b[0]), "r"(b[1]));
}

// ---------------- GEMM core: 128x128 tile, 8 warps (2m x 4n), split-bf16 ---
// D(128, n0+0..127) += A_f32(128 x K) . B^T ; B pre-split bf16 [n][k] rows.
// acc must be zeroed by caller. K chunks of KC=32. 256 threads.
__device__ __forceinline__ void gemm_mma(
    const float* __restrict__ Aop, int lda,
    const __nv_bfloat16* __restrict__ Bh, const __nv_bfloat16* __restrict__ Bl,
    int ldb, int n0, int kbase, int kcnt,
    __nv_bfloat16* sAh, __nv_bfloat16* sAl,
    __nv_bfloat16* sBh, __nv_bfloat16* sBl,
    float (&acc)[4][4][4])
{
    const int tid  = threadIdx.x;
    const int lane = tid & 31, wid = tid >> 5;
    const int wm = (wid & 1) << 6;          // 0 / 64
    const int wn = (wid >> 1) << 5;         // 0 / 32 / 64 / 96
    const int lrow = (lane & 7) + ((lane >> 3) & 1) * 8;   // ldmatrix row 0..15
    const int lko  = (lane >> 4) * 8;                      // ldmatrix k-off 0/8
    const uint32_t uAh = smem_u32(sAh), uAl = smem_u32(sAl);
    const uint32_t uBh = smem_u32(sBh), uBl = smem_u32(sBl);
    const int srow = tid >> 1;
    const int scol = (tid & 1) << 4;        // 0 or 16

    for (int k0 = kbase; k0 < kbase + kcnt; k0 += KC) {
        // ---- stage A (fp32 -> bf16 hi/lo) and B (copy hi/lo) ----
        {
            const float* Ar = Aop + (size_t)srow * lda + k0 + scol;
            uint32_t hw[8], lw[8];
            #pragma unroll
            for (int q = 0; q < 8; ++q) {
                float2 f = *(const float2*)(Ar + 2*q);
                __nv_bfloat16 h0, l0, h1, l1;
                cvt_split(f.x, h0, l0);
                cvt_split(f.y, h1, l1);
                hw[q] = (uint32_t)__bfloat16_as_ushort(h0)
                      | ((uint32_t)__bfloat16_as_ushort(h1) << 16);
                lw[q] = (uint32_t)__bfloat16_as_ushort(l0)
                      | ((uint32_t)__bfloat16_as_ushort(l1) << 16);
            }
            __nv_bfloat16* da = sAh + srow * ASTR + scol;
            *(uint4*)(da)     = make_uint4(hw[0], hw[1], hw[2], hw[3]);
            *(uint4*)(da + 8) = make_uint4(hw[4], hw[5], hw[6], hw[7]);
            __nv_bfloat16* dl = sAl + srow * ASTR + scol;
            *(uint4*)(dl)     = make_uint4(lw[0], lw[1], lw[2], lw[3]);
            *(uint4*)(dl + 8) = make_uint4(lw[4], lw[5], lw[6], lw[7]);

            const __nv_bfloat16* Bhr = Bh + (size_t)(n0 + srow) * ldb + k0 + scol;
            const __nv_bfloat16* Blr = Bl + (size_t)(n0 + srow) * ldb + k0 + scol;
            __nv_bfloat16* db = sBh + srow * ASTR + scol;
            *(uint4*)(db)     = *(const uint4*)(Bhr);
            *(uint4*)(db + 8) = *(const uint4*)(Bhr + 8);
            __nv_bfloat16* db2 = sBl + srow * ASTR + scol;
            *(uint4*)(db2)     = *(const uint4*)(Blr);
            *(uint4*)(db2 + 8) = *(const uint4*)(Blr + 8);
        }
        __syncthreads();

        // ---- compute: 2 k16 steps ----
        #pragma unroll
        for (int kk = 0; kk < KC; kk += 16) {
            uint32_t aH[4][4], aL[4][4], bH[4][2], bL[4][2];
            #pragma unroll
            for (int mf = 0; mf < 4; ++mf) {
                uint32_t off = (uint32_t)((wm + mf*16 + lrow) * ASTR + kk + lko) * 2;
                ldm4(aH[mf], uAh + off);
                ldm4(aL[mf], uAl + off);
            }
            #pragma unroll
            for (int np = 0; np < 2; ++np) {
                uint32_t off = (uint32_t)((wn + np*16 + lrow) * ASTR + kk + lko) * 2;
                uint32_t r[4];
                ldm4(r, uBh + off);
                bH[np*2][0] = r[0]; bH[np*2+1][0] = r[1];
                bH[np*2][1] = r[2]; bH[np*2+1][1] = r[3];
                ldm4(r, uBl + off);
                bL[np*2][0] = r[0]; bL[np*2+1][0] = r[1];
                bL[np*2][1] = r[2]; bL[np*2+1][1] = r[3];
            }
            #pragma unroll
            for (int mf = 0; mf < 4; ++mf)
                #pragma unroll
                for (int nf = 0; nf < 4; ++nf) {
                    mma_bf16(acc[mf][nf], aH[mf], bH[nf]);
                    mma_bf16(acc[mf][nf], aH[mf], bL[nf]);
                    mma_bf16(acc[mf][nf], aL[mf], bH[nf]);
                }
        }
        __syncthreads();
    }
}

__device__ __forceinline__ void store_acc(
    float* __restrict__ dst, int ldo, int n0, float (&acc)[4][4][4])
{
    const int lane = threadIdx.x & 31, wid = threadIdx.x >> 5;
    const int wm = (wid & 1) << 6, wn = (wid >> 1) << 5;
    const int g = lane >> 2, i2 = (lane & 3) << 1;
    #pragma unroll
    for (int mf = 0; mf < 4; ++mf) {
        const int r0 = wm + mf*16 + g;
        #pragma unroll
        for (int nf = 0; nf < 4; ++nf) {
            const int col = n0 + wn + nf*8 + i2;
            *(float2*)(dst + (size_t)r0 * ldo + col)
                = make_float2(acc[mf][nf][0], acc[mf][nf][1]);
            *(float2*)(dst + (size_t)(r0 + 8) * ldo + col)
                = make_float2(acc[mf][nf][2], acc[mf][nf][3]);
        }
    }
}

// K chunk tables: 512 -> {192,192,128} (multiples of KC)
__device__ __constant__ int c_ko[3] = {0, 192, 384};
__device__ __constant__ int c_kc[3] = {192, 192, 128};

// ---------------- the single persistent kernel ------------------------------
__global__ __launch_bounds__(256) void k_persist(
    const float* __restrict__ x,    const float* __restrict__ Wx,
    const float* __restrict__ Wh,   const float* __restrict__ b_lstm,
    const float* __restrict__ Wg_h, const float* __restrict__ Wg_p,
    const float* __restrict__ bg,   const float* __restrict__ Wilc,
    const float* __restrict__ bilc, const float* __restrict__ Wsl,
    const float* __restrict__ bsl,  const float* __restrict__ Wlin,
    const float* __restrict__ blin, float* __restrict__ out)
{
    __shared__ __align__(16) __nv_bfloat16 sAh[128*ASTR];
    __shared__ __align__(16) __nv_bfloat16 sAl[128*ASTR];
    __shared__ __align__(16) __nv_bfloat16 sBh[128*ASTR];
    __shared__ __align__(16) __nv_bfloat16 sBl[128*ASTR];
    float* red = (float*)sAh;   // reduction scratch (combine stage)

    const int P   = gridDim.x;
    const int tid = threadIdx.x;
    const int gthreads = P * 256;
    const int gtid = blockIdx.x * 256 + tid;

    // -------- init states --------
    for (int i = gtid; i < L_*A_*B_*H_; i += gthreads) { g_hs[i] = 0.f; g_cs[i] = 0.f; }
    for (int i = gtid; i < B_*H_; i += gthreads) g_hg[i] = 0.f;

    // -------- weight pre-split (fp32 -> bf16 hi/lo) --------
    for (int i = gtid; i < NWX; i += gthreads) {
        cvt_split(Wx[i], cWx_h[i], cWx_l[i]);
        cvt_split(Wh[i], cWh_h[i], cWh_l[i]);
    }
    for (int i = gtid; i < NWG; i += gthreads) {
        cvt_split(Wg_h[i], cWgh_h[i], cWgh_l[i]);
        cvt_split(Wg_p[i], cWgp_h[i], cWgp_l[i]);
    }
    for (int i = gtid; i < NWSL; i += gthreads)
        cvt_split(Wsl[i], cWsl_h[i], cWsl_l[i]);
    for (int i = gtid; i < NWILC; i += gthreads) {
        int la = i / (Z_*Z_);
        int r  = i - la * (Z_*Z_);
        int y  = r / Z_, z = r - (r / Z_) * Z_;
        cvt_split(Wilc[(size_t)la * Z_ * Z_ + (size_t)z * Z_ + y],
                  cWilc_h[i], cWilc_l[i]);
    }
    gsync();

    for (int t = 0; t < T_; ++t) {
        const float* xt = x + (size_t)t * B_ * H_;

        // ===== Multi-LSTM levels =====
        for (int l = 0; l < L_; ++l) {
            // --- GEMM stage: 288 tensor items (+16 y-items at l==0, t>0) ---
            const int extra = (l == 0 && t > 0) ? 16 : 0;
            for (int w = blockIdx.x; w < 288 + extra; w += P) {
                if (w < 288) {
                    const int ks = w / 48;            // 0..5
                    const int r  = w - ks * 48;
                    const int a  = r >> 4;
                    const int n0 = (r & 15) << 7;
                    const int cc = (ks < 3) ? ks : (ks - 3);
                    const float* src;
                    const __nv_bfloat16 *bh, *bl;
                    size_t woff = (size_t)(a*L_ + l) * 4 * H_ * H_;
                    if (ks < 3) {
                        src = (l == 0) ? xt
                             : (g_hs + ((size_t)(l-1)*A_ + a) * B_ * H_);
                        bh = cWx_h + woff; bl = cWx_l + woff;
                    } else {
                        src = g_hs + ((size_t)l*A_ + a) * B_ * H_;
                        bh = cWh_h + woff; bl = cWh_l + woff;
                    }
                    float acc[4][4][4] = {};
                    gemm_mma(src, H_, bh, bl, H_, n0, c_ko[cc], c_kc[cc],
                             sAh, sAl, sBh, sBl, acc);
                    store_acc(g_prep + (size_t)ks * ABNH4 + (size_t)a * B_ * NH4,
                              NH4, n0, acc);
                } else {
                    const int j    = w - 288;
                    const int warp = tid >> 5, lane = tid & 31;
                    const int b    = j * 8 + warp;
                    const float* h  = g_hg + (size_t)b * H_;
                    const float* wl = Wlin + (size_t)(t-1) * H_;
                    float s = 0.f;
                    for (int k = lane; k < H_; k += 32) s = fmaf(h[k], wl[k], s);
                    #pragma unroll
                    for (int o2 = 16; o2 > 0; o2 >>= 1)
                        s += __shfl_down_sync(0xffffffffu, s, o2);
                    if (lane == 0) out[(size_t)(t-1) * B_ + b] = s + blin[t-1];
                }
            }
            gsync();

            // --- pointwise gates: sum 6 K-split partials, in place hs/cs ---
            for (int idx = gtid; idx < A_*B_*H_; idx += gthreads) {
                int a = idx / (B_*H_);
                int r = idx - a * (B_*H_);
                int b = r / H_;
                int o = r - b * H_;
                size_t base = ((size_t)a * B_ + b) * NH4;
                const float* bb = b_lstm + ((size_t)(a*L_ + l)) * 4 * H_;
                float pi = bb[0*H_ + o], pf = bb[1*H_ + o];
                float pg = bb[2*H_ + o], po = bb[3*H_ + o];
                #pragma unroll
                for (int ks = 0; ks < 6; ++ks) {
                    const float* p = g_prep + (size_t)ks * ABNH4 + base;
                    pi += p[0*H_ + o];
                    pf += p[1*H_ + o];
                    pg += p[2*H_ + o];
                    po += p[3*H_ + o];
                }
                float ig = sigmoidf_(pi);
                float fg = sigmoidf_(pf);
                float gg = tanhf(pg);
                float og = sigmoidf_(po);
                size_t ci = ((size_t)(l*A_ + a) * B_ + b) * H_ + o;
                float c = fg * g_cs[ci] + ig * gg;
                g_cs[ci] = c;
                g_hs[ci] = og * tanhf(c);
            }
            gsync();
        }

        // ===== cell_fn pre GEMM: 1080 items (15 la x 6 ks x 12 ntiles) =====
        for (int w = blockIdx.x; w < 1080; w += P) {
            const int la = w / 72;
            const int r  = w - la * 72;
            const int ks = r / 12;
            const int n0 = (r % 12) << 7;
            const int cc = (ks < 3) ? ks : (ks - 3);
            const float* src;
            const __nv_bfloat16 *bh, *bl;
            size_t woff = (size_t)la * N3Z * H_;
            if (ks < 3) {
                src = g_hg;
                bh = cWgh_h + woff; bl = cWgh_l + woff;
            } else {
                src = g_hs + (size_t)la * B_ * H_;
                bh = cWgp_h + woff; bl = cWgp_l + woff;
            }
            float acc[4][4][4] = {};
            gemm_mma(src, H_, bh, bl, H_, n0, c_ko[cc], c_kc[cc],
                     sAh, sAl, sBh, sBl, acc);
            store_acc(g_pre3 + (size_t)ks * LABN3Z + (size_t)la * B_ * N3Z,
                      N3Z, n0, acc);
        }
        gsync();

        // ===== cell_fn pointwise: sum 6 partials =====
        for (int idx = gtid; idx < LABZ; idx += gthreads) {
            int la = idx / (B_*Z_);
            int r  = idx - la * (B_*Z_);
            int z  = r % Z_;
            size_t base = ((size_t)la * B_ + (r / Z_)) * N3Z;
            const float* bb = bg + (size_t)la * N3Z;
            float vi = bb[0*Z_ + z], vf = bb[1*Z_ + z], vg = bb[2*Z_ + z];
            #pragma unroll
            for (int ks = 0; ks < 6; ++ks) {
                const float* p = g_pre3 + (size_t)ks * LABN3Z + base;
                vi += p[0*Z_ + z];
                vf += p[1*Z_ + z];
                vg += p[2*Z_ + z];
            }
            float ig = sigmoidf_(vi);
            float fg = sigmoidf_(vf);
            float gg = tanhf(vg);
            float ic = ig * g_cs[idx];
            g_icell[idx] = ic;
            g_ccell[idx] = fg * gg + ic;
        }
        gsync();

        // ===== t1/t2 GEMM: 240 items (15 la x {t1,t2} x 2 ks x 4 ntiles) ====
        for (int w = blockIdx.x; w < 240; w += P) {
            const int la = w / 16;
            const int r  = w - la * 16;
            const int which = r >> 3;
            const int rr = r & 7;
            const int ks = rr >> 2;
            const int n0 = (rr & 3) << 7;
            const float* Aop = (which ? g_ccell : g_icell) + (size_t)la * B_ * Z_;
            size_t woff = (size_t)la * Z_ * Z_;
            float acc[4][4][4] = {};
            gemm_mma(Aop, Z_, cWilc_h + woff, cWilc_l + woff, Z_,
                     n0, ks * 256, 256, sAh, sAl, sBh, sBl, acc);
            store_acc((which ? g_t2p : g_t1p)
                      + (size_t)ks * LABZ + (size_t)la * B_ * Z_,
                      Z_, n0, acc);
        }
        gsync();

        // ===== combine: sum axes+ks, sigmoid(t2)*softmax(t1) -> cat =====
        for (int row = blockIdx.x; row < L_*B_; row += P) {
            const int l = row / B_, b = row % B_;
            float t1v[2], t2v[2];
            #pragma unroll
            for (int h = 0; h < 2; ++h) {
                const int y = tid + h*256;
                float sb = bilc[(size_t)(l*A_+0)*Z_ + y]
                         + bilc[(size_t)(l*A_+1)*Z_ + y]
                         + bilc[(size_t)(l*A_+2)*Z_ + y];
                size_t off = (size_t)(l*A_) * B_ * Z_ + (size_t)b * Z_ + y;
                size_t st  = (size_t)B_ * Z_;
                const float* p1 = g_t1p + off;
                const float* p2 = g_t2p + off;
                t1v[h] = p1[0] + p1[st] + p1[2*st]
                       + p1[LABZ] + p1[LABZ+st] + p1[LABZ+2*st] + sb;
                t2v[h] = p2[0] + p2[st] + p2[2*st]
                       + p2[LABZ] + p2[LABZ+st] + p2[LABZ+2*st] + sb;
            }
            red[tid] = fmaxf(t1v[0], t1v[1]);
            __syncthreads();
            for (int s = 128; s > 0; s >>= 1) {
                if (tid < s) red[tid] = fmaxf(red[tid], red[tid + s]);
                __syncthreads();
            }
            float M = red[0];
            __syncthreads();
            float e0 = expf(t1v[0] - M), e1 = expf(t1v[1] - M);
            red[tid] = e0 + e1;
            __syncthreads();
            for (int s = 128; s > 0; s >>= 1) {
                if (tid < s) red[tid] += red[tid + s];
                __syncthreads();
            }
            float inv = 1.f / red[0];
            __syncthreads();
            float* cat = g_cat + (size_t)b * LZ + (size_t)l * Z_;
            cat[tid      ] = sigmoidf_(t2v[0]) * e0 * inv;
            cat[tid + 256] = sigmoidf_(t2v[1]) * e1 * inv;
        }
        gsync();

        // ===== single_li GEMM: 40 items (10 K-chunks x 4 ntiles) =====
        for (int w = blockIdx.x; w < 40; w += P) {
            const int ks = w >> 2;
            const int n0 = (w & 3) << 7;
            float acc[4][4][4] = {};
            gemm_mma(g_cat, LZ, cWsl_h, cWsl_l, LZ,
                     n0, ks * 256, 256, sAh, sAl, sBh, sBl, acc);
            store_acc(g_hgp + (size_t)ks * B_ * H_, H_, n0, acc);
        }
        gsync();

        // ===== reduce 10 splits + bias -> h_g =====
        for (int idx = gtid; idx < B_*H_; idx += gthreads) {
            float s = bsl[idx % H_];
            #pragma unroll
            for (int ks = 0; ks < 10; ++ks) s += g_hgp[(size_t)ks * B_ * H_ + idx];
            g_hg[idx] = s;
        }
        gsync();
    }

    // ===== final y for t = T-1 =====
    for (int w = blockIdx.x; w < 16; w += P) {
        const int warp = tid >> 5, lane = tid & 31;
        const int b    = w * 8 + warp;
        const float* h  = g_hg + (size_t)b * H_;
        const float* wl = Wlin + (size_t)(T_-1) * H_;
        float s = 0.f;
        for (int k = lane; k < H_; k += 32) s = fmaf(h[k], wl[k], s);
        #pragma unroll
        for (int o2 = 16; o2 > 0; o2 >>= 1) s += __shfl_down_sync(0xffffffffu, s, o2);
        if (lane == 0) out[(size_t)(T_-1) * B_ + b] = s + blin[T_-1];
    }
}

// ---------------- host orchestration ---------------------------------------
extern "C" void kernel_launch(void* const* d_in, const int* in_sizes, int n_in,
                              void* d_out, int out_size)
{
    const float* x      = (const float*)d_in[0];
    const float* Wx     = (const float*)d_in[1];
    const float* Wh     = (const float*)d_in[2];
    const float* b_lstm = (const float*)d_in[3];
    const float* Wg_h   = (const float*)d_in[4];
    const float* Wg_p   = (const float*)d_in[5];
    const float* bg     = (const float*)d_in[6];
    const float* Wilc   = (const float*)d_in[7];
    const float* bilc   = (const float*)d_in[8];
    const float* Wsl    = (const float*)d_in[9];
    const float* bsl    = (const float*)d_in[10];
    const float* Wlin   = (const float*)d_in[11];
    const float* blin   = (const float*)d_in[12];
    float* out = (float*)d_out;

    // Safe co-resident grid size (recomputed every call; deterministic).
    int dev = 0;
    cudaGetDevice(&dev);
    int sms = 148;
    cudaDeviceGetAttribute(&sms, cudaDevAttrMultiProcessorCount, dev);
    int bpm = 1;
    cudaOccupancyMaxActiveBlocksPerMultiprocessor(&bpm, k_persist, 256, 0);
    if (bpm < 1) bpm = 1;
    if (bpm > 2) bpm = 2;
    int P = sms * bpm;

    k_persist<<<P, 256>>>(x, Wx, Wh, b_lstm, Wg_h, Wg_p, bg, Wilc, bilc,
                          Wsl, bsl, Wlin, blin, out);
}

// round 13
// speedup vs baseline: 2.4609x; 1.3835x over previous
#include <cuda_runtime.h>
#include <cuda_bf16.h>
#include <math.h>
#include <stdint.h>

#define T_ 64
#define B_ 128
#define H_ 512
#define A_ 3
#define L_ 5
#define Z_ 512
#define NH4 (4*H_)      /* 2048 */
#define N3Z (3*Z_)      /* 1536 */
#define LZ  (L_*Z_)     /* 2560 */

#define ABNH4  (A_*B_*NH4)
#define LABZ   (L_*A_*B_*Z_)
#define LABN3Z (L_*A_*B_*N3Z)

#define NWX   (A_*L_*4*H_*H_)      /* 15728640 */
#define NWG   (L_*A_*3*Z_*H_)      /* 11796480 */
#define NWILC (L_*A_*Z_*Z_)        /* 3932160  */
#define NWSL  (H_*LZ)              /* 1310720  */

#define KC   32                     /* K chunk staged in smem */
#define APAD 8
#define ASTR (KC + APAD)            /* 40 elems = 80 B row stride */

// ---------------- persistent scratch (device globals; no allocation) -------
__device__ float g_hs[L_*A_*B_*H_];
__device__ float g_cs[L_*A_*B_*H_];
__device__ float g_hg[B_*H_];
__device__ float g_prep[6*ABNH4];
__device__ float g_pre3[6*LABN3Z];
__device__ float g_icell[LABZ];
__device__ float g_ccell[LABZ];
__device__ float g_t1p[2*LABZ];
__device__ float g_t2p[2*LABZ];
__device__ float g_hgp[10*B_*H_];
__device__ float g_cat[B_*LZ];

// pre-split bf16 weights (hi/lo), converted once per launch
__device__ __nv_bfloat16 cWx_h[NWX],   cWx_l[NWX];
__device__ __nv_bfloat16 cWh_h[NWX],   cWh_l[NWX];
__device__ __nv_bfloat16 cWgh_h[NWG],  cWgh_l[NWG];
__device__ __nv_bfloat16 cWgp_h[NWG],  cWgp_l[NWG];
__device__ __nv_bfloat16 cWilc_h[NWILC], cWilc_l[NWILC];   // TRANSPOSED [la][y][z]
__device__ __nv_bfloat16 cWsl_h[NWSL], cWsl_l[NWSL];

// ---------------- grid barrier ---------------------------------------------
__device__ unsigned g_cnt = 0;
__device__ volatile unsigned g_gen = 0;

__device__ __forceinline__ void gsync() {
    __syncthreads();
    if (threadIdx.x == 0) {
        unsigned gen = g_gen;
        __threadfence();
        if (atomicAdd(&g_cnt, 1u) == gridDim.x - 1) {
            g_cnt = 0;
            __threadfence();
            g_gen = gen + 1u;
        } else {
            while (g_gen == gen) { __nanosleep(32); }
        }
        __threadfence();
    }
    __syncthreads();
}

__device__ __forceinline__ float sigmoidf_(float x) { return 1.f / (1.f + expf(-x)); }

__device__ __forceinline__ void cvt_split(float x, __nv_bfloat16& h, __nv_bfloat16& l) {
    h = __float2bfloat16_rn(x);
    l = __float2bfloat16_rn(x - __bfloat162float(h));
}

__device__ __forceinline__ uint32_t smem_u32(const void* p) {
    uint32_t a;
    asm("{ .reg .u64 t; cvta.to.shared.u64 t, %1; cvt.u32.u64 %0, t; }"
        : "=r"(a) : "l"(p));
    return a;
}

// ---------------- baseline (non-'a') tensor ops: ldmatrix + mma.sync -------
__device__ __forceinline__ void ldm4(uint32_t* r, uint32_t addr) {
    asm volatile("ldmatrix.sync.aligned.m8n8.x4.shared.b16 {%0,%1,%2,%3}, [%4];"
        : "=r"(r[0]), "=r"(r[1]), "=r"(r[2]), "=r"(r[3]) : "r"(addr));
}
__device__ __forceinline__ void mma_bf16(float* c, const uint32_t* a,
                                         const uint32_t* b) {
    asm volatile(
        "mma.sync.aligned.m16n8k16.row.col.f32.bf16.bf16.f32 "
        "{%0,%1,%2,%3}, {%4,%5,%6,%7}, {%8,%9}, {%0,%1,%2,%3};"
        : "+f"(c[0]), "+f"(c[1]), "+f"(c[2]), "+f"(c[3])
        : "r"(a[0]), "r"(a[1]), "r"(a[2]), "r"(a[3]), "r"(b[0]), "r"(b[1]));
}

// ---------------- GEMM core: 128x128 tile, 8 warps (2m x 4n), split-bf16 ---
// D(128, n0+0..127) += A_f32(128 x K) . B^T ; B pre-split bf16 [n][k] rows.
// acc must be zeroed by caller. K chunks of KC=32. 256 threads.
__device__ __forceinline__ void gemm_mma(
    const float* __restrict__ Aop, int lda,
    const __nv_bfloat16* __restrict__ Bh, const __nv_bfloat16* __restrict__ Bl,
    int ldb, int n0, int kbase, int kcnt,
    __nv_bfloat16* sAh, __nv_bfloat16* sAl,
    __nv_bfloat16* sBh, __nv_bfloat16* sBl,
    float (&acc)[4][4][4])
{
    const int tid  = threadIdx.x;
    const int lane = tid & 31, wid = tid >> 5;
    const int wm = (wid & 1) << 6;          // 0 / 64
    const int wn = (wid >> 1) << 5;         // 0 / 32 / 64 / 96
    const int lrow = (lane & 7) + ((lane >> 3) & 1) * 8;   // ldmatrix row 0..15
    const int lko  = (lane >> 4) * 8;                      // ldmatrix k-off 0/8
    const uint32_t uAh = smem_u32(sAh), uAl = smem_u32(sAl);
    const uint32_t uBh = smem_u32(sBh), uBl = smem_u32(sBl);
    const int srow = tid >> 1;
    const int scol = (tid & 1) << 4;        // 0 or 16

    for (int k0 = kbase; k0 < kbase + kcnt; k0 += KC) {
        // ---- stage A (fp32 -> bf16 hi/lo) and B (copy hi/lo) ----
        {
            const float* Ar = Aop + (size_t)srow * lda + k0 + scol;
            uint32_t hw[8], lw[8];
            #pragma unroll
            for (int q = 0; q < 8; ++q) {
                float2 f = *(const float2*)(Ar + 2*q);
                __nv_bfloat16 h0, l0, h1, l1;
                cvt_split(f.x, h0, l0);
                cvt_split(f.y, h1, l1);
                hw[q] = (uint32_t)__bfloat16_as_ushort(h0)
                      | ((uint32_t)__bfloat16_as_ushort(h1) << 16);
                lw[q] = (uint32_t)__bfloat16_as_ushort(l0)
                      | ((uint32_t)__bfloat16_as_ushort(l1) << 16);
            }
            __nv_bfloat16* da = sAh + srow * ASTR + scol;
            *(uint4*)(da)     = make_uint4(hw[0], hw[1], hw[2], hw[3]);
            *(uint4*)(da + 8) = make_uint4(hw[4], hw[5], hw[6], hw[7]);
            __nv_bfloat16* dl = sAl + srow * ASTR + scol;
            *(uint4*)(dl)     = make_uint4(lw[0], lw[1], lw[2], lw[3]);
            *(uint4*)(dl + 8) = make_uint4(lw[4], lw[5], lw[6], lw[7]);

            const __nv_bfloat16* Bhr = Bh + (size_t)(n0 + srow) * ldb + k0 + scol;
            const __nv_bfloat16* Blr = Bl + (size_t)(n0 + srow) * ldb + k0 + scol;
            __nv_bfloat16* db = sBh + srow * ASTR + scol;
            *(uint4*)(db)     = *(const uint4*)(Bhr);
            *(uint4*)(db + 8) = *(const uint4*)(Bhr + 8);
            __nv_bfloat16* db2 = sBl + srow * ASTR + scol;
            *(uint4*)(db2)     = *(const uint4*)(Blr);
            *(uint4*)(db2 + 8) = *(const uint4*)(Blr + 8);
        }
        __syncthreads();

        // ---- compute: 2 k16 steps ----
        #pragma unroll
        for (int kk = 0; kk < KC; kk += 16) {
            uint32_t aH[4][4], aL[4][4], bH[4][2], bL[4][2];
            #pragma unroll
            for (int mf = 0; mf < 4; ++mf) {
                uint32_t off = (uint32_t)((wm + mf*16 + lrow) * ASTR + kk + lko) * 2;
                ldm4(aH[mf], uAh + off);
                ldm4(aL[mf], uAl + off);
            }
            #pragma unroll
            for (int np = 0; np < 2; ++np) {
                uint32_t off = (uint32_t)((wn + np*16 + lrow) * ASTR + kk + lko) * 2;
                uint32_t r[4];
                ldm4(r, uBh + off);
                bH[np*2][0] = r[0]; bH[np*2+1][0] = r[1];
                bH[np*2][1] = r[2]; bH[np*2+1][1] = r[3];
                ldm4(r, uBl + off);
                bL[np*2][0] = r[0]; bL[np*2+1][0] = r[1];
                bL[np*2][1] = r[2]; bL[np*2+1][1] = r[3];
            }
            #pragma unroll
            for (int mf = 0; mf < 4; ++mf)
                #pragma unroll
                for (int nf = 0; nf < 4; ++nf) {
                    mma_bf16(acc[mf][nf], aH[mf], bH[nf]);
                    mma_bf16(acc[mf][nf], aH[mf], bL[nf]);
                    mma_bf16(acc[mf][nf], aL[mf], bH[nf]);
                }
        }
        __syncthreads();
    }
}

__device__ __forceinline__ void store_acc(
    float* __restrict__ dst, int ldo, int n0, float (&acc)[4][4][4])
{
    const int lane = threadIdx.x & 31, wid = threadIdx.x >> 5;
    const int wm = (wid & 1) << 6, wn = (wid >> 1) << 5;
    const int g = lane >> 2, i2 = (lane & 3) << 1;
    #pragma unroll
    for (int mf = 0; mf < 4; ++mf) {
        const int r0 = wm + mf*16 + g;
        #pragma unroll
        for (int nf = 0; nf < 4; ++nf) {
            const int col = n0 + wn + nf*8 + i2;
            *(float2*)(dst + (size_t)r0 * ldo + col)
                = make_float2(acc[mf][nf][0], acc[mf][nf][1]);
            *(float2*)(dst + (size_t)(r0 + 8) * ldo + col)
                = make_float2(acc[mf][nf][2], acc[mf][nf][3]);
        }
    }
}

// K chunk tables: 512 -> {192,192,128} (multiples of KC)
__device__ __constant__ int c_ko[3] = {0, 192, 384};
__device__ __constant__ int c_kc[3] = {192, 192, 128};

// ---------------- the single persistent kernel ------------------------------
__global__ __launch_bounds__(256, 2) void k_persist(
    const float* __restrict__ x,    const float* __restrict__ Wx,
    const float* __restrict__ Wh,   const float* __restrict__ b_lstm,
    const float* __restrict__ Wg_h, const float* __restrict__ Wg_p,
    const float* __restrict__ bg,   const float* __restrict__ Wilc,
    const float* __restrict__ bilc, const float* __restrict__ Wsl,
    const float* __restrict__ bsl,  const float* __restrict__ Wlin,
    const float* __restrict__ blin, float* __restrict__ out)
{
    __shared__ __align__(16) __nv_bfloat16 sAh[128*ASTR];
    __shared__ __align__(16) __nv_bfloat16 sAl[128*ASTR];
    __shared__ __align__(16) __nv_bfloat16 sBh[128*ASTR];
    __shared__ __align__(16) __nv_bfloat16 sBl[128*ASTR];
    float* red = (float*)sAh;   // reduction scratch (combine stage)

    const int P   = gridDim.x;
    const int tid = threadIdx.x;
    const int gthreads = P * 256;
    const int gtid = blockIdx.x * 256 + tid;

    // -------- init states --------
    for (int i = gtid; i < L_*A_*B_*H_; i += gthreads) { g_hs[i] = 0.f; g_cs[i] = 0.f; }
    for (int i = gtid; i < B_*H_; i += gthreads) g_hg[i] = 0.f;

    // -------- weight pre-split (fp32 -> bf16 hi/lo) --------
    for (int i = gtid; i < NWX; i += gthreads) {
        cvt_split(Wx[i], cWx_h[i], cWx_l[i]);
        cvt_split(Wh[i], cWh_h[i], cWh_l[i]);
    }
    for (int i = gtid; i < NWG; i += gthreads) {
        cvt_split(Wg_h[i], cWgh_h[i], cWgh_l[i]);
        cvt_split(Wg_p[i], cWgp_h[i], cWgp_l[i]);
    }
    for (int i = gtid; i < NWSL; i += gthreads)
        cvt_split(Wsl[i], cWsl_h[i], cWsl_l[i]);
    for (int i = gtid; i < NWILC; i += gthreads) {
        int la = i / (Z_*Z_);
        int r  = i - la * (Z_*Z_);
        int y  = r / Z_, z = r - (r / Z_) * Z_;
        cvt_split(Wilc[(size_t)la * Z_ * Z_ + (size_t)z * Z_ + y],
                  cWilc_h[i], cWilc_l[i]);
    }
    gsync();

    for (int t = 0; t < T_; ++t) {
        const float* xt = x + (size_t)t * B_ * H_;

        // ===== Multi-LSTM levels =====
        for (int l = 0; l < L_; ++l) {
            // --- GEMM stage: 288 tensor items (+16 y-items at l==0, t>0) ---
            const int extra = (l == 0 && t > 0) ? 16 : 0;
            for (int w = blockIdx.x; w < 288 + extra; w += P) {
                if (w < 288) {
                    const int ks = w / 48;            // 0..5
                    const int r  = w - ks * 48;
                    const int a  = r >> 4;
                    const int n0 = (r & 15) << 7;
                    const int cc = (ks < 3) ? ks : (ks - 3);
                    const float* src;
                    const __nv_bfloat16 *bh, *bl;
                    size_t woff = (size_t)(a*L_ + l) * 4 * H_ * H_;
                    if (ks < 3) {
                        src = (l == 0) ? xt
                             : (g_hs + ((size_t)(l-1)*A_ + a) * B_ * H_);
                        bh = cWx_h + woff; bl = cWx_l + woff;
                    } else {
                        src = g_hs + ((size_t)l*A_ + a) * B_ * H_;
                        bh = cWh_h + woff; bl = cWh_l + woff;
                    }
                    float acc[4][4][4] = {};
                    gemm_mma(src, H_, bh, bl, H_, n0, c_ko[cc], c_kc[cc],
                             sAh, sAl, sBh, sBl, acc);
                    store_acc(g_prep + (size_t)ks * ABNH4 + (size_t)a * B_ * NH4,
                              NH4, n0, acc);
                } else {
                    const int j    = w - 288;
                    const int warp = tid >> 5, lane = tid & 31;
                    const int b    = j * 8 + warp;
                    const float* h  = g_hg + (size_t)b * H_;
                    const float* wl = Wlin + (size_t)(t-1) * H_;
                    float s = 0.f;
                    for (int k = lane; k < H_; k += 32) s = fmaf(h[k], wl[k], s);
                    #pragma unroll
                    for (int o2 = 16; o2 > 0; o2 >>= 1)
                        s += __shfl_down_sync(0xffffffffu, s, o2);
                    if (lane == 0) out[(size_t)(t-1) * B_ + b] = s + blin[t-1];
                }
            }
            gsync();

            // --- pointwise gates: sum 6 K-split partials, in place hs/cs ---
            for (int idx = gtid; idx < A_*B_*H_; idx += gthreads) {
                int a = idx / (B_*H_);
                int r = idx - a * (B_*H_);
                int b = r / H_;
                int o = r - b * H_;
                size_t base = ((size_t)a * B_ + b) * NH4;
                const float* bb = b_lstm + ((size_t)(a*L_ + l)) * 4 * H_;
                float pi = bb[0*H_ + o], pf = bb[1*H_ + o];
                float pg = bb[2*H_ + o], po = bb[3*H_ + o];
                #pragma unroll
                for (int ks = 0; ks < 6; ++ks) {
                    const float* p = g_prep + (size_t)ks * ABNH4 + base;
                    pi += p[0*H_ + o];
                    pf += p[1*H_ + o];
                    pg += p[2*H_ + o];
                    po += p[3*H_ + o];
                }
                float ig = sigmoidf_(pi);
                float fg = sigmoidf_(pf);
                float gg = tanhf(pg);
                float og = sigmoidf_(po);
                size_t ci = ((size_t)(l*A_ + a) * B_ + b) * H_ + o;
                float c = fg * g_cs[ci] + ig * gg;
                g_cs[ci] = c;
                g_hs[ci] = og * tanhf(c);
            }
            gsync();
        }

        // ===== cell_fn pre GEMM: 1080 items (15 la x 6 ks x 12 ntiles) =====
        for (int w = blockIdx.x; w < 1080; w += P) {
            const int la = w / 72;
            const int r  = w - la * 72;
            const int ks = r / 12;
            const int n0 = (r % 12) << 7;
            const int cc = (ks < 3) ? ks : (ks - 3);
            const float* src;
            const __nv_bfloat16 *bh, *bl;
            size_t woff = (size_t)la * N3Z * H_;
            if (ks < 3) {
                src = g_hg;
                bh = cWgh_h + woff; bl = cWgh_l + woff;
            } else {
                src = g_hs + (size_t)la * B_ * H_;
                bh = cWgp_h + woff; bl = cWgp_l + woff;
            }
            float acc[4][4][4] = {};
            gemm_mma(src, H_, bh, bl, H_, n0, c_ko[cc], c_kc[cc],
                     sAh, sAl, sBh, sBl, acc);
            store_acc(g_pre3 + (size_t)ks * LABN3Z + (size_t)la * B_ * N3Z,
                      N3Z, n0, acc);
        }
        gsync();

        // ===== cell_fn pointwise: sum 6 partials =====
        for (int idx = gtid; idx < LABZ; idx += gthreads) {
            int la = idx / (B_*Z_);
            int r  = idx - la * (B_*Z_);
            int z  = r % Z_;
            size_t base = ((size_t)la * B_ + (r / Z_)) * N3Z;
            const float* bb = bg + (size_t)la * N3Z;
            float vi = bb[0*Z_ + z], vf = bb[1*Z_ + z], vg = bb[2*Z_ + z];
            #pragma unroll
            for (int ks = 0; ks < 6; ++ks) {
                const float* p = g_pre3 + (size_t)ks * LABN3Z + base;
                vi += p[0*Z_ + z];
                vf += p[1*Z_ + z];
                vg += p[2*Z_ + z];
            }
            float ig = sigmoidf_(vi);
            float fg = sigmoidf_(vf);
            float gg = tanhf(vg);
            float ic = ig * g_cs[idx];
            g_icell[idx] = ic;
            g_ccell[idx] = fg * gg + ic;
        }
        gsync();

        // ===== t1/t2 GEMM: 240 items (15 la x {t1,t2} x 2 ks x 4 ntiles) ====
        for (int w = blockIdx.x; w < 240; w += P) {
            const int la = w / 16;
            const int r  = w - la * 16;
            const int which = r >> 3;
            const int rr = r & 7;
            const int ks = rr >> 2;
            const int n0 = (rr & 3) << 7;
            const float* Aop = (which ? g_ccell : g_icell) + (size_t)la * B_ * Z_;
            size_t woff = (size_t)la * Z_ * Z_;
            float acc[4][4][4] = {};
            gemm_mma(Aop, Z_, cWilc_h + woff, cWilc_l + woff, Z_,
                     n0, ks * 256, 256, sAh, sAl, sBh, sBl, acc);
            store_acc((which ? g_t2p : g_t1p)
                      + (size_t)ks * LABZ + (size_t)la * B_ * Z_,
                      Z_, n0, acc);
        }
        gsync();

        // ===== combine: sum axes+ks, sigmoid(t2)*softmax(t1) -> cat =====
        for (int row = blockIdx.x; row < L_*B_; row += P) {
            const int l = row / B_, b = row % B_;
            float t1v[2], t2v[2];
            #pragma unroll
            for (int h = 0; h < 2; ++h) {
                const int y = tid + h*256;
                float sb = bilc[(size_t)(l*A_+0)*Z_ + y]
                         + bilc[(size_t)(l*A_+1)*Z_ + y]
                         + bilc[(size_t)(l*A_+2)*Z_ + y];
                size_t off = (size_t)(l*A_) * B_ * Z_ + (size_t)b * Z_ + y;
                size_t st  = (size_t)B_ * Z_;
                const float* p1 = g_t1p + off;
                const float* p2 = g_t2p + off;
                t1v[h] = p1[0] + p1[st] + p1[2*st]
                       + p1[LABZ] + p1[LABZ+st] + p1[LABZ+2*st] + sb;
                t2v[h] = p2[0] + p2[st] + p2[2*st]
                       + p2[LABZ] + p2[LABZ+st] + p2[LABZ+2*st] + sb;
            }
            red[tid] = fmaxf(t1v[0], t1v[1]);
            __syncthreads();
            for (int s = 128; s > 0; s >>= 1) {
                if (tid < s) red[tid] = fmaxf(red[tid], red[tid + s]);
                __syncthreads();
            }
            float M = red[0];
            __syncthreads();
            float e0 = expf(t1v[0] - M), e1 = expf(t1v[1] - M);
            red[tid] = e0 + e1;
            __syncthreads();
            for (int s = 128; s > 0; s >>= 1) {
                if (tid < s) red[tid] += red[tid + s];
                __syncthreads();
            }
            float inv = 1.f / red[0];
            __syncthreads();
            float* cat = g_cat + (size_t)b * LZ + (size_t)l * Z_;
            cat[tid      ] = sigmoidf_(t2v[0]) * e0 * inv;
            cat[tid + 256] = sigmoidf_(t2v[1]) * e1 * inv;
        }
        gsync();

        // ===== single_li GEMM: 40 items (10 K-chunks x 4 ntiles) =====
        for (int w = blockIdx.x; w < 40; w += P) {
            const int ks = w >> 2;
            const int n0 = (w & 3) << 7;
            float acc[4][4][4] = {};
            gemm_mma(g_cat, LZ, cWsl_h, cWsl_l, LZ,
                     n0, ks * 256, 256, sAh, sAl, sBh, sBl, acc);
            store_acc(g_hgp + (size_t)ks * B_ * H_, H_, n0, acc);
        }
        gsync();

        // ===== reduce 10 splits + bias -> h_g =====
        for (int idx = gtid; idx < B_*H_; idx += gthreads) {
            float s = bsl[idx % H_];
            #pragma unroll
            for (int ks = 0; ks < 10; ++ks) s += g_hgp[(size_t)ks * B_ * H_ + idx];
            g_hg[idx] = s;
        }
        gsync();
    }

    // ===== final y for t = T-1 =====
    for (int w = blockIdx.x; w < 16; w += P) {
        const int warp = tid >> 5, lane = tid & 31;
        const int b    = w * 8 + warp;
        const float* h  = g_hg + (size_t)b * H_;
        const float* wl = Wlin + (size_t)(T_-1) * H_;
        float s = 0.f;
        for (int k = lane; k < H_; k += 32) s = fmaf(h[k], wl[k], s);
        #pragma unroll
        for (int o2 = 16; o2 > 0; o2 >>= 1) s += __shfl_down_sync(0xffffffffu, s, o2);
        if (lane == 0) out[(size_t)(T_-1) * B_ + b] = s + blin[T_-1];
    }
}

// ---------------- host orchestration ---------------------------------------
extern "C" void kernel_launch(void* const* d_in, const int* in_sizes, int n_in,
                              void* d_out, int out_size)
{
    const float* x      = (const float*)d_in[0];
    const float* Wx     = (const float*)d_in[1];
    const float* Wh     = (const float*)d_in[2];
    const float* b_lstm = (const float*)d_in[3];
    const float* Wg_h   = (const float*)d_in[4];
    const float* Wg_p   = (const float*)d_in[5];
    const float* bg     = (const float*)d_in[6];
    const float* Wilc   = (const float*)d_in[7];
    const float* bilc   = (const float*)d_in[8];
    const float* Wsl    = (const float*)d_in[9];
    const float* bsl    = (const float*)d_in[10];
    const float* Wlin   = (const float*)d_in[11];
    const float* blin   = (const float*)d_in[12];
    float* out = (float*)d_out;

    // Safe co-resident grid size (recomputed every call; deterministic).
    int dev = 0;
    cudaGetDevice(&dev);
    int sms = 148;
    cudaDeviceGetAttribute(&sms, cudaDevAttrMultiProcessorCount, dev);
    int bpm = 1;
    cudaOccupancyMaxActiveBlocksPerMultiprocessor(&bpm, k_persist, 256, 0);
    if (bpm < 1) bpm = 1;
    if (bpm > 2) bpm = 2;
    int P = sms * bpm;

    k_persist<<<P, 256>>>(x, Wx, Wh, b_lstm, Wg_h, Wg_p, bg, Wilc, bilc,
                          Wsl, bsl, Wlin, blin, out);
}

// round 14
// speedup vs baseline: 2.5894x; 1.0522x over previous
#include <cuda_runtime.h>
#include <cuda_bf16.h>
#include <math.h>
#include <stdint.h>

#define T_ 64
#define B_ 128
#define H_ 512
#define A_ 3
#define L_ 5
#define Z_ 512
#define NH4 (4*H_)      /* 2048 */
#define N3Z (3*Z_)      /* 1536 */
#define LZ  (L_*Z_)     /* 2560 */

#define ABNH4  (A_*B_*NH4)
#define LABZ   (L_*A_*B_*Z_)
#define LABN3Z (L_*A_*B_*N3Z)

#define NWX   (A_*L_*4*H_*H_)      /* 15728640 */
#define NWG   (L_*A_*3*Z_*H_)      /* 11796480 */
#define NWILC (L_*A_*Z_*Z_)        /* 3932160  */
#define NWSL  (H_*LZ)              /* 1310720  */

#define KC   64                     /* K chunk staged in smem */
#define APAD 8
#define ASTR (KC + APAD)            /* 72 elems = 144 B row stride */
#define TILE_ELEMS (128*ASTR)       /* per smem tile */
#define SMEM_DYN (4*TILE_ELEMS*2)   /* 73728 B */

// ---------------- persistent scratch (device globals; no allocation) -------
__device__ float g_hs[L_*A_*B_*H_];
__device__ float g_cs[L_*A_*B_*H_];
__device__ float g_hg[B_*H_];
__device__ float g_prep[6*ABNH4];
__device__ float g_pre3[6*LABN3Z];
__device__ float g_icell[LABZ];
__device__ float g_ccell[LABZ];
__device__ float g_t1p[2*LABZ];
__device__ float g_t2p[2*LABZ];
__device__ float g_hgp[10*B_*H_];
__device__ float g_cat[B_*LZ];

// pre-split bf16 weights (hi/lo), converted once per launch
__device__ __nv_bfloat16 cWx_h[NWX],   cWx_l[NWX];
__device__ __nv_bfloat16 cWh_h[NWX],   cWh_l[NWX];
__device__ __nv_bfloat16 cWgh_h[NWG],  cWgh_l[NWG];
__device__ __nv_bfloat16 cWgp_h[NWG],  cWgp_l[NWG];
__device__ __nv_bfloat16 cWilc_h[NWILC], cWilc_l[NWILC];   // TRANSPOSED [la][y][z]
__device__ __nv_bfloat16 cWsl_h[NWSL], cWsl_l[NWSL];

// ---------------- grid barrier ---------------------------------------------
__device__ unsigned g_cnt = 0;
__device__ volatile unsigned g_gen = 0;

__device__ __forceinline__ void gsync() {
    __syncthreads();
    if (threadIdx.x == 0) {
        unsigned gen = g_gen;
        __threadfence();
        if (atomicAdd(&g_cnt, 1u) == gridDim.x - 1) {
            g_cnt = 0;
            __threadfence();
            g_gen = gen + 1u;
        } else {
            while (g_gen == gen) { __nanosleep(32); }
        }
        __threadfence();
    }
    __syncthreads();
}

__device__ __forceinline__ float sigmoidf_(float x) { return 1.f / (1.f + expf(-x)); }

__device__ __forceinline__ void cvt_split(float x, __nv_bfloat16& h, __nv_bfloat16& l) {
    h = __float2bfloat16_rn(x);
    l = __float2bfloat16_rn(x - __bfloat162float(h));
}

__device__ __forceinline__ uint32_t smem_u32(const void* p) {
    uint32_t a;
    asm("{ .reg .u64 t; cvta.to.shared.u64 t, %1; cvt.u32.u64 %0, t; }"
        : "=r"(a) : "l"(p));
    return a;
}

// ---------------- baseline (non-'a') tensor ops: ldmatrix + mma.sync -------
__device__ __forceinline__ void ldm4(uint32_t* r, uint32_t addr) {
    asm volatile("ldmatrix.sync.aligned.m8n8.x4.shared.b16 {%0,%1,%2,%3}, [%4];"
        : "=r"(r[0]), "=r"(r[1]), "=r"(r[2]), "=r"(r[3]) : "r"(addr));
}
__device__ __forceinline__ void mma_bf16(float* c, const uint32_t* a,
                                         const uint32_t* b) {
    asm volatile(
        "mma.sync.aligned.m16n8k16.row.col.f32.bf16.bf16.f32 "
        "{%0,%1,%2,%3}, {%4,%5,%6,%7}, {%8,%9}, {%0,%1,%2,%3};"
        : "+f"(c[0]), "+f"(c[1]), "+f"(c[2]), "+f"(c[3])
        : "r"(a[0]), "r"(a[1]), "r"(a[2]), "r"(a[3]), "r"(b[0]), "r"(b[1]));
}

// ---------------- GEMM core: 128x128 tile, 8 warps (2m x 4n), split-bf16 ---
// D(128, n0+0..127) += A_f32(128 x K) . B^T ; B pre-split bf16 [n][k] rows.
// acc must be zeroed by caller. K chunks of KC=64. 256 threads.
__device__ __forceinline__ void gemm_mma(
    const float* __restrict__ Aop, int lda,
    const __nv_bfloat16* __restrict__ Bh, const __nv_bfloat16* __restrict__ Bl,
    int ldb, int n0, int kbase, int kcnt,
    __nv_bfloat16* sAh, __nv_bfloat16* sAl,
    __nv_bfloat16* sBh, __nv_bfloat16* sBl,
    float (&acc)[4][4][4])
{
    const int tid  = threadIdx.x;
    const int lane = tid & 31, wid = tid >> 5;
    const int wm = (wid & 1) << 6;          // 0 / 64
    const int wn = (wid >> 1) << 5;         // 0 / 32 / 64 / 96
    const int lrow = (lane & 7) + ((lane >> 3) & 1) * 8;   // ldmatrix row 0..15
    const int lko  = (lane >> 4) * 8;                      // ldmatrix k-off 0/8
    const uint32_t uAh = smem_u32(sAh), uAl = smem_u32(sAl);
    const uint32_t uBh = smem_u32(sBh), uBl = smem_u32(sBl);
    const int srow = tid >> 1;
    const int scol = (tid & 1) << 5;        // 0 or 32

    for (int k0 = kbase; k0 < kbase + kcnt; k0 += KC) {
        // ---- stage A (fp32 -> bf16 hi/lo, float4 loads) and B (copy) ----
        {
            const float* Ar = Aop + (size_t)srow * lda + k0 + scol;
            uint32_t hw[16], lw[16];
            #pragma unroll
            for (int q = 0; q < 8; ++q) {
                float4 f = *(const float4*)(Ar + 4*q);
                __nv_bfloat16 h0, l0, h1, l1, h2, l2, h3, l3;
                cvt_split(f.x, h0, l0);
                cvt_split(f.y, h1, l1);
                cvt_split(f.z, h2, l2);
                cvt_split(f.w, h3, l3);
                hw[2*q]   = (uint32_t)__bfloat16_as_ushort(h0)
                          | ((uint32_t)__bfloat16_as_ushort(h1) << 16);
                hw[2*q+1] = (uint32_t)__bfloat16_as_ushort(h2)
                          | ((uint32_t)__bfloat16_as_ushort(h3) << 16);
                lw[2*q]   = (uint32_t)__bfloat16_as_ushort(l0)
                          | ((uint32_t)__bfloat16_as_ushort(l1) << 16);
                lw[2*q+1] = (uint32_t)__bfloat16_as_ushort(l2)
                          | ((uint32_t)__bfloat16_as_ushort(l3) << 16);
            }
            __nv_bfloat16* da = sAh + srow * ASTR + scol;
            *(uint4*)(da)      = make_uint4(hw[0],  hw[1],  hw[2],  hw[3]);
            *(uint4*)(da + 8)  = make_uint4(hw[4],  hw[5],  hw[6],  hw[7]);
            *(uint4*)(da + 16) = make_uint4(hw[8],  hw[9],  hw[10], hw[11]);
            *(uint4*)(da + 24) = make_uint4(hw[12], hw[13], hw[14], hw[15]);
            __nv_bfloat16* dl = sAl + srow * ASTR + scol;
            *(uint4*)(dl)      = make_uint4(lw[0],  lw[1],  lw[2],  lw[3]);
            *(uint4*)(dl + 8)  = make_uint4(lw[4],  lw[5],  lw[6],  lw[7]);
            *(uint4*)(dl + 16) = make_uint4(lw[8],  lw[9],  lw[10], lw[11]);
            *(uint4*)(dl + 24) = make_uint4(lw[12], lw[13], lw[14], lw[15]);

            const __nv_bfloat16* Bhr = Bh + (size_t)(n0 + srow) * ldb + k0 + scol;
            const __nv_bfloat16* Blr = Bl + (size_t)(n0 + srow) * ldb + k0 + scol;
            __nv_bfloat16* db = sBh + srow * ASTR + scol;
            *(uint4*)(db)      = *(const uint4*)(Bhr);
            *(uint4*)(db + 8)  = *(const uint4*)(Bhr + 8);
            *(uint4*)(db + 16) = *(const uint4*)(Bhr + 16);
            *(uint4*)(db + 24) = *(const uint4*)(Bhr + 24);
            __nv_bfloat16* db2 = sBl + srow * ASTR + scol;
            *(uint4*)(db2)      = *(const uint4*)(Blr);
            *(uint4*)(db2 + 8)  = *(const uint4*)(Blr + 8);
            *(uint4*)(db2 + 16) = *(const uint4*)(Blr + 16);
            *(uint4*)(db2 + 24) = *(const uint4*)(Blr + 24);
        }
        __syncthreads();

        // ---- compute: 4 k16 steps ----
        #pragma unroll
        for (int kk = 0; kk < KC; kk += 16) {
            uint32_t aH[4][4], aL[4][4], bH[4][2], bL[4][2];
            #pragma unroll
            for (int mf = 0; mf < 4; ++mf) {
                uint32_t off = (uint32_t)((wm + mf*16 + lrow) * ASTR + kk + lko) * 2;
                ldm4(aH[mf], uAh + off);
                ldm4(aL[mf], uAl + off);
            }
            #pragma unroll
            for (int np = 0; np < 2; ++np) {
                uint32_t off = (uint32_t)((wn + np*16 + lrow) * ASTR + kk + lko) * 2;
                uint32_t r[4];
                ldm4(r, uBh + off);
                bH[np*2][0] = r[0]; bH[np*2+1][0] = r[1];
                bH[np*2][1] = r[2]; bH[np*2+1][1] = r[3];
                ldm4(r, uBl + off);
                bL[np*2][0] = r[0]; bL[np*2+1][0] = r[1];
                bL[np*2][1] = r[2]; bL[np*2+1][1] = r[3];
            }
            #pragma unroll
            for (int mf = 0; mf < 4; ++mf)
                #pragma unroll
                for (int nf = 0; nf < 4; ++nf) {
                    mma_bf16(acc[mf][nf], aH[mf], bH[nf]);
                    mma_bf16(acc[mf][nf], aH[mf], bL[nf]);
                    mma_bf16(acc[mf][nf], aL[mf], bH[nf]);
                }
        }
        __syncthreads();
    }
}

__device__ __forceinline__ void store_acc(
    float* __restrict__ dst, int ldo, int n0, float (&acc)[4][4][4])
{
    const int lane = threadIdx.x & 31, wid = threadIdx.x >> 5;
    const int wm = (wid & 1) << 6, wn = (wid >> 1) << 5;
    const int g = lane >> 2, i2 = (lane & 3) << 1;
    #pragma unroll
    for (int mf = 0; mf < 4; ++mf) {
        const int r0 = wm + mf*16 + g;
        #pragma unroll
        for (int nf = 0; nf < 4; ++nf) {
            const int col = n0 + wn + nf*8 + i2;
            *(float2*)(dst + (size_t)r0 * ldo + col)
                = make_float2(acc[mf][nf][0], acc[mf][nf][1]);
            *(float2*)(dst + (size_t)(r0 + 8) * ldo + col)
                = make_float2(acc[mf][nf][2], acc[mf][nf][3]);
        }
    }
}

// K chunk tables: 512 -> {192,192,128} (multiples of KC)
__device__ __constant__ int c_ko[3] = {0, 192, 384};
__device__ __constant__ int c_kc[3] = {192, 192, 128};

// ---------------- the single persistent kernel ------------------------------
__global__ __launch_bounds__(256, 2) void k_persist(
    const float* __restrict__ x,    const float* __restrict__ Wx,
    const float* __restrict__ Wh,   const float* __restrict__ b_lstm,
    const float* __restrict__ Wg_h, const float* __restrict__ Wg_p,
    const float* __restrict__ bg,   const float* __restrict__ Wilc,
    const float* __restrict__ bilc, const float* __restrict__ Wsl,
    const float* __restrict__ bsl,  const float* __restrict__ Wlin,
    const float* __restrict__ blin, float* __restrict__ out)
{
    extern __shared__ __align__(16) __nv_bfloat16 dsm[];
    __nv_bfloat16* sAh = dsm;
    __nv_bfloat16* sAl = dsm + TILE_ELEMS;
    __nv_bfloat16* sBh = dsm + 2*TILE_ELEMS;
    __nv_bfloat16* sBl = dsm + 3*TILE_ELEMS;
    float* red = (float*)dsm;   // reduction scratch (combine stage)

    const int P   = gridDim.x;
    const int tid = threadIdx.x;
    const int gthreads = P * 256;
    const int gtid = blockIdx.x * 256 + tid;

    // -------- init states --------
    for (int i = gtid; i < L_*A_*B_*H_; i += gthreads) { g_hs[i] = 0.f; g_cs[i] = 0.f; }
    for (int i = gtid; i < B_*H_; i += gthreads) g_hg[i] = 0.f;

    // -------- weight pre-split (fp32 -> bf16 hi/lo) --------
    for (int i = gtid; i < NWX; i += gthreads) {
        cvt_split(Wx[i], cWx_h[i], cWx_l[i]);
        cvt_split(Wh[i], cWh_h[i], cWh_l[i]);
    }
    for (int i = gtid; i < NWG; i += gthreads) {
        cvt_split(Wg_h[i], cWgh_h[i], cWgh_l[i]);
        cvt_split(Wg_p[i], cWgp_h[i], cWgp_l[i]);
    }
    for (int i = gtid; i < NWSL; i += gthreads)
        cvt_split(Wsl[i], cWsl_h[i], cWsl_l[i]);
    for (int i = gtid; i < NWILC; i += gthreads) {
        int la = i / (Z_*Z_);
        int r  = i - la * (Z_*Z_);
        int y  = r / Z_, z = r - (r / Z_) * Z_;
        cvt_split(Wilc[(size_t)la * Z_ * Z_ + (size_t)z * Z_ + y],
                  cWilc_h[i], cWilc_l[i]);
    }
    gsync();

    for (int t = 0; t < T_; ++t) {
        const float* xt = x + (size_t)t * B_ * H_;

        // ===== Multi-LSTM levels =====
        for (int l = 0; l < L_; ++l) {
            // --- GEMM stage: 288 tensor items (+16 y-items at l==0, t>0) ---
            const int extra = (l == 0 && t > 0) ? 16 : 0;
            for (int w = blockIdx.x; w < 288 + extra; w += P) {
                if (w < 288) {
                    const int ks = w / 48;            // 0..5
                    const int r  = w - ks * 48;
                    const int a  = r >> 4;
                    const int n0 = (r & 15) << 7;
                    const int cc = (ks < 3) ? ks : (ks - 3);
                    const float* src;
                    const __nv_bfloat16 *bh, *bl;
                    size_t woff = (size_t)(a*L_ + l) * 4 * H_ * H_;
                    if (ks < 3) {
                        src = (l == 0) ? xt
                             : (g_hs + ((size_t)(l-1)*A_ + a) * B_ * H_);
                        bh = cWx_h + woff; bl = cWx_l + woff;
                    } else {
                        src = g_hs + ((size_t)l*A_ + a) * B_ * H_;
                        bh = cWh_h + woff; bl = cWh_l + woff;
                    }
                    float acc[4][4][4] = {};
                    gemm_mma(src, H_, bh, bl, H_, n0, c_ko[cc], c_kc[cc],
                             sAh, sAl, sBh, sBl, acc);
                    store_acc(g_prep + (size_t)ks * ABNH4 + (size_t)a * B_ * NH4,
                              NH4, n0, acc);
                } else {
                    const int j    = w - 288;
                    const int warp = tid >> 5, lane = tid & 31;
                    const int b    = j * 8 + warp;
                    const float* h  = g_hg + (size_t)b * H_;
                    const float* wl = Wlin + (size_t)(t-1) * H_;
                    float s = 0.f;
                    for (int k = lane; k < H_; k += 32) s = fmaf(h[k], wl[k], s);
                    #pragma unroll
                    for (int o2 = 16; o2 > 0; o2 >>= 1)
                        s += __shfl_down_sync(0xffffffffu, s, o2);
                    if (lane == 0) out[(size_t)(t-1) * B_ + b] = s + blin[t-1];
                }
            }
            gsync();

            // --- pointwise gates: sum 6 K-split partials, in place hs/cs ---
            for (int idx = gtid; idx < A_*B_*H_; idx += gthreads) {
                int a = idx / (B_*H_);
                int r = idx - a * (B_*H_);
                int b = r / H_;
                int o = r - b * H_;
                size_t base = ((size_t)a * B_ + b) * NH4;
                const float* bb = b_lstm + ((size_t)(a*L_ + l)) * 4 * H_;
                float pi = bb[0*H_ + o], pf = bb[1*H_ + o];
                float pg = bb[2*H_ + o], po = bb[3*H_ + o];
                #pragma unroll
                for (int ks = 0; ks < 6; ++ks) {
                    const float* p = g_prep + (size_t)ks * ABNH4 + base;
                    pi += p[0*H_ + o];
                    pf += p[1*H_ + o];
                    pg += p[2*H_ + o];
                    po += p[3*H_ + o];
                }
                float ig = sigmoidf_(pi);
                float fg = sigmoidf_(pf);
                float gg = tanhf(pg);
                float og = sigmoidf_(po);
                size_t ci = ((size_t)(l*A_ + a) * B_ + b) * H_ + o;
                float c = fg * g_cs[ci] + ig * gg;
                g_cs[ci] = c;
                g_hs[ci] = og * tanhf(c);
            }
            gsync();
        }

        // ===== cell_fn pre GEMM: 1080 items (15 la x 6 ks x 12 ntiles) =====
        for (int w = blockIdx.x; w < 1080; w += P) {
            const int la = w / 72;
            const int r  = w - la * 72;
            const int ks = r / 12;
            const int n0 = (r % 12) << 7;
            const int cc = (ks < 3) ? ks : (ks - 3);
            const float* src;
            const __nv_bfloat16 *bh, *bl;
            size_t woff = (size_t)la * N3Z * H_;
            if (ks < 3) {
                src = g_hg;
                bh = cWgh_h + woff; bl = cWgh_l + woff;
            } else {
                src = g_hs + (size_t)la * B_ * H_;
                bh = cWgp_h + woff; bl = cWgp_l + woff;
            }
            float acc[4][4][4] = {};
            gemm_mma(src, H_, bh, bl, H_, n0, c_ko[cc], c_kc[cc],
                     sAh, sAl, sBh, sBl, acc);
            store_acc(g_pre3 + (size_t)ks * LABN3Z + (size_t)la * B_ * N3Z,
                      N3Z, n0, acc);
        }
        gsync();

        // ===== cell_fn pointwise: sum 6 partials =====
        for (int idx = gtid; idx < LABZ; idx += gthreads) {
            int la = idx / (B_*Z_);
            int r  = idx - la * (B_*Z_);
            int z  = r % Z_;
            size_t base = ((size_t)la * B_ + (r / Z_)) * N3Z;
            const float* bb = bg + (size_t)la * N3Z;
            float vi = bb[0*Z_ + z], vf = bb[1*Z_ + z], vg = bb[2*Z_ + z];
            #pragma unroll
            for (int ks = 0; ks < 6; ++ks) {
                const float* p = g_pre3 + (size_t)ks * LABN3Z + base;
                vi += p[0*Z_ + z];
                vf += p[1*Z_ + z];
                vg += p[2*Z_ + z];
            }
            float ig = sigmoidf_(vi);
            float fg = sigmoidf_(vf);
            float gg = tanhf(vg);
            float ic = ig * g_cs[idx];
            g_icell[idx] = ic;
            g_ccell[idx] = fg * gg + ic;
        }
        gsync();

        // ===== t1/t2 GEMM: 240 items (15 la x {t1,t2} x 2 ks x 4 ntiles) ====
        for (int w = blockIdx.x; w < 240; w += P) {
            const int la = w / 16;
            const int r  = w - la * 16;
            const int which = r >> 3;
            const int rr = r & 7;
            const int ks = rr >> 2;
            const int n0 = (rr & 3) << 7;
            const float* Aop = (which ? g_ccell : g_icell) + (size_t)la * B_ * Z_;
            size_t woff = (size_t)la * Z_ * Z_;
            float acc[4][4][4] = {};
            gemm_mma(Aop, Z_, cWilc_h + woff, cWilc_l + woff, Z_,
                     n0, ks * 256, 256, sAh, sAl, sBh, sBl, acc);
            store_acc((which ? g_t2p : g_t1p)
                      + (size_t)ks * LABZ + (size_t)la * B_ * Z_,
                      Z_, n0, acc);
        }
        gsync();

        // ===== combine: sum axes+ks, sigmoid(t2)*softmax(t1) -> cat =====
        for (int row = blockIdx.x; row < L_*B_; row += P) {
            const int l = row / B_, b = row % B_;
            float t1v[2], t2v[2];
            #pragma unroll
            for (int h = 0; h < 2; ++h) {
                const int y = tid + h*256;
                float sb = bilc[(size_t)(l*A_+0)*Z_ + y]
                         + bilc[(size_t)(l*A_+1)*Z_ + y]
                         + bilc[(size_t)(l*A_+2)*Z_ + y];
                size_t off = (size_t)(l*A_) * B_ * Z_ + (size_t)b * Z_ + y;
                size_t st  = (size_t)B_ * Z_;
                const float* p1 = g_t1p + off;
                const float* p2 = g_t2p + off;
                t1v[h] = p1[0] + p1[st] + p1[2*st]
                       + p1[LABZ] + p1[LABZ+st] + p1[LABZ+2*st] + sb;
                t2v[h] = p2[0] + p2[st] + p2[2*st]
                       + p2[LABZ] + p2[LABZ+st] + p2[LABZ+2*st] + sb;
            }
            red[tid] = fmaxf(t1v[0], t1v[1]);
            __syncthreads();
            for (int s = 128; s > 0; s >>= 1) {
                if (tid < s) red[tid] = fmaxf(red[tid], red[tid + s]);
                __syncthreads();
            }
            float M = red[0];
            __syncthreads();
            float e0 = expf(t1v[0] - M), e1 = expf(t1v[1] - M);
            red[tid] = e0 + e1;
            __syncthreads();
            for (int s = 128; s > 0; s >>= 1) {
                if (tid < s) red[tid] += red[tid + s];
                __syncthreads();
            }
            float inv = 1.f / red[0];
            __syncthreads();
            float* cat = g_cat + (size_t)b * LZ + (size_t)l * Z_;
            cat[tid      ] = sigmoidf_(t2v[0]) * e0 * inv;
            cat[tid + 256] = sigmoidf_(t2v[1]) * e1 * inv;
        }
        gsync();

        // ===== single_li GEMM: 40 items (10 K-chunks x 4 ntiles) =====
        for (int w = blockIdx.x; w < 40; w += P) {
            const int ks = w >> 2;
            const int n0 = (w & 3) << 7;
            float acc[4][4][4] = {};
            gemm_mma(g_cat, LZ, cWsl_h, cWsl_l, LZ,
                     n0, ks * 256, 256, sAh, sAl, sBh, sBl, acc);
            store_acc(g_hgp + (size_t)ks * B_ * H_, H_, n0, acc);
        }
        gsync();

        // ===== reduce 10 splits + bias -> h_g =====
        for (int idx = gtid; idx < B_*H_; idx += gthreads) {
            float s = bsl[idx % H_];
            #pragma unroll
            for (int ks = 0; ks < 10; ++ks) s += g_hgp[(size_t)ks * B_ * H_ + idx];
            g_hg[idx] = s;
        }
        gsync();
    }

    // ===== final y for t = T-1 =====
    for (int w = blockIdx.x; w < 16; w += P) {
        const int warp = tid >> 5, lane = tid & 31;
        const int b    = w * 8 + warp;
        const float* h  = g_hg + (size_t)b * H_;
        const float* wl = Wlin + (size_t)(T_-1) * H_;
        float s = 0.f;
        for (int k = lane; k < H_; k += 32) s = fmaf(h[k], wl[k], s);
        #pragma unroll
        for (int o2 = 16; o2 > 0; o2 >>= 1) s += __shfl_down_sync(0xffffffffu, s, o2);
        if (lane == 0) out[(size_t)(T_-1) * B_ + b] = s + blin[T_-1];
    }
}

// ---------------- host orchestration ---------------------------------------
extern "C" void kernel_launch(void* const* d_in, const int* in_sizes, int n_in,
                              void* d_out, int out_size)
{
    const float* x      = (const float*)d_in[0];
    const float* Wx     = (const float*)d_in[1];
    const float* Wh     = (const float*)d_in[2];
    const float* b_lstm = (const float*)d_in[3];
    const float* Wg_h   = (const float*)d_in[4];
    const float* Wg_p   = (const float*)d_in[5];
    const float* bg     = (const float*)d_in[6];
    const float* Wilc   = (const float*)d_in[7];
    const float* bilc   = (const float*)d_in[8];
    const float* Wsl    = (const float*)d_in[9];
    const float* bsl    = (const float*)d_in[10];
    const float* Wlin   = (const float*)d_in[11];
    const float* blin   = (const float*)d_in[12];
    float* out = (float*)d_out;

    cudaFuncSetAttribute(k_persist, cudaFuncAttributeMaxDynamicSharedMemorySize,
                         SMEM_DYN);

    // Safe co-resident grid size (recomputed every call; deterministic).
    int dev = 0;
    cudaGetDevice(&dev);
    int sms = 148;
    cudaDeviceGetAttribute(&sms, cudaDevAttrMultiProcessorCount, dev);
    int bpm = 1;
    cudaOccupancyMaxActiveBlocksPerMultiprocessor(&bpm, k_persist, 256, SMEM_DYN);
    if (bpm < 1) bpm = 1;
    if (bpm > 2) bpm = 2;
    int P = sms * bpm;

    k_persist<<<P, 256, SMEM_DYN>>>(x, Wx, Wh, b_lstm, Wg_h, Wg_p, bg, Wilc,
                                    bilc, Wsl, bsl, Wlin, blin, out);
}

// round 15
// speedup vs baseline: 2.6717x; 1.0318x over previous
#include <cuda_runtime.h>
#include <cuda_bf16.h>
#include <math.h>
#include <stdint.h>

#define T_ 64
#define B_ 128
#define H_ 512
#define A_ 3
#define L_ 5
#define Z_ 512
#define NH4 (4*H_)      /* 2048 */
#define N3Z (3*Z_)      /* 1536 */
#define LZ  (L_*Z_)     /* 2560 */

#define ABNH4  (A_*B_*NH4)
#define LABZ   (L_*A_*B_*Z_)
#define LABN3Z (L_*A_*B_*N3Z)
#define LABH   (L_*A_*B_*H_)

#define NWX   (A_*L_*4*H_*H_)      /* 15728640 */
#define NWG   (L_*A_*3*Z_*H_)      /* 11796480 */
#define NWILC (L_*A_*Z_*Z_)        /* 3932160  */
#define NWSL  (H_*LZ)              /* 1310720  */

#define KC   32                     /* K chunk staged in smem */
#define APAD 8
#define ASTR (KC + APAD)            /* 40 elems = 80 B row stride */
#define TILE_ELEMS (128*ASTR)       /* 5120 elems = 10240 B */
#define TILE_BYTES (TILE_ELEMS*2)
#define BUF_BYTES  (4*TILE_BYTES)   /* 40960 B per buffer */
#define SMEM_DYN   (2*BUF_BYTES)    /* 81920 B */

// ---------------- persistent scratch (device globals; no allocation) -------
__device__ float g_cs[LABH];
__device__ float g_hg[B_*H_];
__device__ float g_prep[6*ABNH4];
__device__ float g_pre3[6*LABN3Z];
__device__ float g_t1p[2*LABZ];
__device__ float g_t2p[2*LABZ];
__device__ float g_hgp[10*B_*H_];

// pre-converted activations (bf16 hi/lo)
__device__ __nv_bfloat16 g_xh[B_*H_],  g_xl[B_*H_];
__device__ __nv_bfloat16 g_hsh[LABH],  g_hsl[LABH];
__device__ __nv_bfloat16 g_hgh[B_*H_], g_hgl[B_*H_];
__device__ __nv_bfloat16 g_ich[LABZ],  g_icl[LABZ];
__device__ __nv_bfloat16 g_cch[LABZ],  g_ccl[LABZ];
__device__ __nv_bfloat16 g_cath[B_*LZ], g_catl[B_*LZ];

// pre-split bf16 weights (hi/lo), converted once per launch
__device__ __nv_bfloat16 cWx_h[NWX],   cWx_l[NWX];
__device__ __nv_bfloat16 cWh_h[NWX],   cWh_l[NWX];
__device__ __nv_bfloat16 cWgh_h[NWG],  cWgh_l[NWG];
__device__ __nv_bfloat16 cWgp_h[NWG],  cWgp_l[NWG];
__device__ __nv_bfloat16 cWilc_h[NWILC], cWilc_l[NWILC];   // TRANSPOSED [la][y][z]
__device__ __nv_bfloat16 cWsl_h[NWSL], cWsl_l[NWSL];

// ---------------- grid barrier ---------------------------------------------
__device__ unsigned g_cnt = 0;
__device__ volatile unsigned g_gen = 0;

__device__ __forceinline__ void gsync() {
    __syncthreads();
    if (threadIdx.x == 0) {
        unsigned gen = g_gen;
        __threadfence();
        if (atomicAdd(&g_cnt, 1u) == gridDim.x - 1) {
            g_cnt = 0;
            __threadfence();
            g_gen = gen + 1u;
        } else {
            while (g_gen == gen) { __nanosleep(32); }
        }
        __threadfence();
    }
    __syncthreads();
}

__device__ __forceinline__ float sigmoidf_(float x) { return 1.f / (1.f + expf(-x)); }

__device__ __forceinline__ void cvt_split(float x, __nv_bfloat16& h, __nv_bfloat16& l) {
    h = __float2bfloat16_rn(x);
    l = __float2bfloat16_rn(x - __bfloat162float(h));
}

__device__ __forceinline__ uint32_t smem_u32(const void* p) {
    uint32_t a;
    asm("{ .reg .u64 t; cvta.to.shared.u64 t, %1; cvt.u32.u64 %0, t; }"
        : "=r"(a) : "l"(p));
    return a;
}

// ---------------- cp.async + tensor ops (all baseline sm_80+) --------------
__device__ __forceinline__ void cp16(uint32_t dst, const void* src) {
    asm volatile("cp.async.cg.shared.global [%0], [%1], 16;"
        :: "r"(dst), "l"(src) : "memory");
}
#define CP_COMMIT() asm volatile("cp.async.commit_group;" ::: "memory")
#define CP_WAIT(n)  asm volatile("cp.async.wait_group %0;" :: "n"(n) : "memory")

__device__ __forceinline__ void ldm4(uint32_t* r, uint32_t addr) {
    asm volatile("ldmatrix.sync.aligned.m8n8.x4.shared.b16 {%0,%1,%2,%3}, [%4];"
        : "=r"(r[0]), "=r"(r[1]), "=r"(r[2]), "=r"(r[3]) : "r"(addr));
}
__device__ __forceinline__ void mma_bf16(float* c, const uint32_t* a,
                                         const uint32_t* b) {
    asm volatile(
        "mma.sync.aligned.m16n8k16.row.col.f32.bf16.bf16.f32 "
        "{%0,%1,%2,%3}, {%4,%5,%6,%7}, {%8,%9}, {%0,%1,%2,%3};"
        : "+f"(c[0]), "+f"(c[1]), "+f"(c[2]), "+f"(c[3])
        : "r"(a[0]), "r"(a[1]), "r"(a[2]), "r"(a[3]), "r"(b[0]), "r"(b[1]));
}

// stage one KC=32 chunk of 4 tiles (Ah, Al, Bh, Bl) via cp.async
__device__ __forceinline__ void stage_chunk(
    const __nv_bfloat16* __restrict__ Ah, const __nv_bfloat16* __restrict__ Al,
    int lda,
    const __nv_bfloat16* __restrict__ Bh, const __nv_bfloat16* __restrict__ Bl,
    int ldb, int n0, int k0, uint32_t ubuf)
{
    const int tid = threadIdx.x;
    const int row = tid >> 1;
    const int he  = (tid & 1) << 4;          // elem offset 0 / 16
    uint32_t d = ubuf + (uint32_t)(row * ASTR + he) * 2;
    const __nv_bfloat16* pa = Ah + (size_t)row * lda + k0 + he;
    cp16(d, pa);                     cp16(d + 16, pa + 8);
    const __nv_bfloat16* pl = Al + (size_t)row * lda + k0 + he;
    cp16(d + TILE_BYTES, pl);        cp16(d + TILE_BYTES + 16, pl + 8);
    const __nv_bfloat16* pb = Bh + (size_t)(n0 + row) * ldb + k0 + he;
    cp16(d + 2*TILE_BYTES, pb);      cp16(d + 2*TILE_BYTES + 16, pb + 8);
    const __nv_bfloat16* pq = Bl + (size_t)(n0 + row) * ldb + k0 + he;
    cp16(d + 3*TILE_BYTES, pq);      cp16(d + 3*TILE_BYTES + 16, pq + 8);
}

// ---------------- GEMM core: 128x128 tile, 8 warps, cp.async pipelined -----
__device__ __forceinline__ void gemm_mma(
    const __nv_bfloat16* __restrict__ Ah, const __nv_bfloat16* __restrict__ Al,
    int lda,
    const __nv_bfloat16* __restrict__ Bh, const __nv_bfloat16* __restrict__ Bl,
    int ldb, int n0, int kbase, int kcnt, uint32_t usmem,
    float (&acc)[4][4][4])
{
    const int tid  = threadIdx.x;
    const int lane = tid & 31, wid = tid >> 5;
    const int wm = (wid & 1) << 6;          // 0 / 64
    const int wn = (wid >> 1) << 5;         // 0 / 32 / 64 / 96
    const int lrow = (lane & 7) + ((lane >> 3) & 1) * 8;   // ldmatrix row 0..15
    const int lko  = (lane >> 4) * 8;                      // ldmatrix k-off 0/8

    const int nch = kcnt / KC;
    stage_chunk(Ah, Al, lda, Bh, Bl, ldb, n0, kbase, usmem);
    CP_COMMIT();
    int cur = 0;
    for (int ch = 0; ch < nch; ++ch) {
        if (ch + 1 < nch) {
            stage_chunk(Ah, Al, lda, Bh, Bl, ldb, n0, kbase + (ch+1)*KC,
                        usmem + (cur^1)*BUF_BYTES);
            CP_COMMIT();
            CP_WAIT(1);
        } else {
            CP_WAIT(0);
        }
        __syncthreads();
        const uint32_t uAh = usmem + cur*BUF_BYTES;
        const uint32_t uAl = uAh + TILE_BYTES;
        const uint32_t uBh = uAh + 2*TILE_BYTES;
        const uint32_t uBl = uAh + 3*TILE_BYTES;
        #pragma unroll
        for (int kk = 0; kk < KC; kk += 16) {
            uint32_t aH[4][4], aL[4][4], bH[4][2], bL[4][2];
            #pragma unroll
            for (int mf = 0; mf < 4; ++mf) {
                uint32_t off = (uint32_t)((wm + mf*16 + lrow) * ASTR + kk + lko) * 2;
                ldm4(aH[mf], uAh + off);
                ldm4(aL[mf], uAl + off);
            }
            #pragma unroll
            for (int np = 0; np < 2; ++np) {
                uint32_t off = (uint32_t)((wn + np*16 + lrow) * ASTR + kk + lko) * 2;
                uint32_t r[4];
                ldm4(r, uBh + off);
                bH[np*2][0] = r[0]; bH[np*2+1][0] = r[1];
                bH[np*2][1] = r[2]; bH[np*2+1][1] = r[3];
                ldm4(r, uBl + off);
                bL[np*2][0] = r[0]; bL[np*2+1][0] = r[1];
                bL[np*2][1] = r[2]; bL[np*2+1][1] = r[3];
            }
            #pragma unroll
            for (int mf = 0; mf < 4; ++mf)
                #pragma unroll
                for (int nf = 0; nf < 4; ++nf) {
                    mma_bf16(acc[mf][nf], aH[mf], bH[nf]);
                    mma_bf16(acc[mf][nf], aH[mf], bL[nf]);
                    mma_bf16(acc[mf][nf], aL[mf], bH[nf]);
                }
        }
        __syncthreads();
        cur ^= 1;
    }
}

__device__ __forceinline__ void store_acc(
    float* __restrict__ dst, int ldo, int n0, float (&acc)[4][4][4])
{
    const int lane = threadIdx.x & 31, wid = threadIdx.x >> 5;
    const int wm = (wid & 1) << 6, wn = (wid >> 1) << 5;
    const int g = lane >> 2, i2 = (lane & 3) << 1;
    #pragma unroll
    for (int mf = 0; mf < 4; ++mf) {
        const int r0 = wm + mf*16 + g;
        #pragma unroll
        for (int nf = 0; nf < 4; ++nf) {
            const int col = n0 + wn + nf*8 + i2;
            *(float2*)(dst + (size_t)r0 * ldo + col)
                = make_float2(acc[mf][nf][0], acc[mf][nf][1]);
            *(float2*)(dst + (size_t)(r0 + 8) * ldo + col)
                = make_float2(acc[mf][nf][2], acc[mf][nf][3]);
        }
    }
}

// K chunk tables: 512 -> {192,192,128} (multiples of KC)
__device__ __constant__ int c_ko[3] = {0, 192, 384};
__device__ __constant__ int c_kc[3] = {192, 192, 128};

// ---------------- the single persistent kernel ------------------------------
__global__ __launch_bounds__(256, 2) void k_persist(
    const float* __restrict__ x,    const float* __restrict__ Wx,
    const float* __restrict__ Wh,   const float* __restrict__ b_lstm,
    const float* __restrict__ Wg_h, const float* __restrict__ Wg_p,
    const float* __restrict__ bg,   const float* __restrict__ Wilc,
    const float* __restrict__ bilc, const float* __restrict__ Wsl,
    const float* __restrict__ bsl,  const float* __restrict__ Wlin,
    const float* __restrict__ blin, float* __restrict__ out)
{
    extern __shared__ __align__(16) char dsm[];
    const uint32_t usmem = smem_u32(dsm);
    float* red = (float*)dsm;   // reduction scratch (combine stage)

    const int P   = gridDim.x;
    const int tid = threadIdx.x;
    const int gthreads = P * 256;
    const int gtid = blockIdx.x * 256 + tid;
    const __nv_bfloat16 bz = __float2bfloat16_rn(0.f);

    // -------- init states + convert x[0] --------
    for (int i = gtid; i < LABH; i += gthreads) {
        g_cs[i] = 0.f; g_hsh[i] = bz; g_hsl[i] = bz;
    }
    for (int i = gtid; i < B_*H_; i += gthreads) {
        g_hg[i] = 0.f; g_hgh[i] = bz; g_hgl[i] = bz;
        cvt_split(x[i], g_xh[i], g_xl[i]);
    }

    // -------- weight pre-split (fp32 -> bf16 hi/lo) --------
    for (int i = gtid; i < NWX; i += gthreads) {
        cvt_split(Wx[i], cWx_h[i], cWx_l[i]);
        cvt_split(Wh[i], cWh_h[i], cWh_l[i]);
    }
    for (int i = gtid; i < NWG; i += gthreads) {
        cvt_split(Wg_h[i], cWgh_h[i], cWgh_l[i]);
        cvt_split(Wg_p[i], cWgp_h[i], cWgp_l[i]);
    }
    for (int i = gtid; i < NWSL; i += gthreads)
        cvt_split(Wsl[i], cWsl_h[i], cWsl_l[i]);
    for (int i = gtid; i < NWILC; i += gthreads) {
        int la = i / (Z_*Z_);
        int r  = i - la * (Z_*Z_);
        int y  = r / Z_, z = r - (r / Z_) * Z_;
        cvt_split(Wilc[(size_t)la * Z_ * Z_ + (size_t)z * Z_ + y],
                  cWilc_h[i], cWilc_l[i]);
    }
    gsync();

    for (int t = 0; t < T_; ++t) {
        // ===== Multi-LSTM levels =====
        for (int l = 0; l < L_; ++l) {
            // --- GEMM stage: 288 tensor items (+16 y-items at l==0, t>0) ---
            const int extra = (l == 0 && t > 0) ? 16 : 0;
            for (int w = blockIdx.x; w < 288 + extra; w += P) {
                if (w < 288) {
                    const int ks = w / 48;            // 0..5
                    const int r  = w - ks * 48;
                    const int a  = r >> 4;
                    const int n0 = (r & 15) << 7;
                    const int cc = (ks < 3) ? ks : (ks - 3);
                    const __nv_bfloat16 *ah, *al, *bh, *bl;
                    size_t woff = (size_t)(a*L_ + l) * 4 * H_ * H_;
                    if (ks < 3) {
                        if (l == 0) { ah = g_xh; al = g_xl; }
                        else {
                            size_t o2 = ((size_t)(l-1)*A_ + a) * B_ * H_;
                            ah = g_hsh + o2; al = g_hsl + o2;
                        }
                        bh = cWx_h + woff; bl = cWx_l + woff;
                    } else {
                        size_t o2 = ((size_t)l*A_ + a) * B_ * H_;
                        ah = g_hsh + o2; al = g_hsl + o2;
                        bh = cWh_h + woff; bl = cWh_l + woff;
                    }
                    float acc[4][4][4] = {};
                    gemm_mma(ah, al, H_, bh, bl, H_, n0, c_ko[cc], c_kc[cc],
                             usmem, acc);
                    store_acc(g_prep + (size_t)ks * ABNH4 + (size_t)a * B_ * NH4,
                              NH4, n0, acc);
                } else {
                    const int j    = w - 288;
                    const int warp = tid >> 5, lane = tid & 31;
                    const int b    = j * 8 + warp;
                    const float* h  = g_hg + (size_t)b * H_;
                    const float* wl = Wlin + (size_t)(t-1) * H_;
                    float s = 0.f;
                    for (int k = lane; k < H_; k += 32) s = fmaf(h[k], wl[k], s);
                    #pragma unroll
                    for (int o2 = 16; o2 > 0; o2 >>= 1)
                        s += __shfl_down_sync(0xffffffffu, s, o2);
                    if (lane == 0) out[(size_t)(t-1) * B_ + b] = s + blin[t-1];
                }
            }
            gsync();

            // --- pointwise gates: sum 6 K-split partials, write hs hi/lo ---
            for (int idx = gtid; idx < A_*B_*H_; idx += gthreads) {
                int a = idx / (B_*H_);
                int r = idx - a * (B_*H_);
                int b = r / H_;
                int o = r - b * H_;
                size_t base = ((size_t)a * B_ + b) * NH4;
                const float* bb = b_lstm + ((size_t)(a*L_ + l)) * 4 * H_;
                float pi = bb[0*H_ + o], pf = bb[1*H_ + o];
                float pg = bb[2*H_ + o], po = bb[3*H_ + o];
                #pragma unroll
                for (int ks = 0; ks < 6; ++ks) {
                    const float* p = g_prep + (size_t)ks * ABNH4 + base;
                    pi += p[0*H_ + o];
                    pf += p[1*H_ + o];
                    pg += p[2*H_ + o];
                    po += p[3*H_ + o];
                }
                float ig = sigmoidf_(pi);
                float fg = sigmoidf_(pf);
                float gg = tanhf(pg);
                float og = sigmoidf_(po);
                size_t ci = ((size_t)(l*A_ + a) * B_ + b) * H_ + o;
                float c = fg * g_cs[ci] + ig * gg;
                g_cs[ci] = c;
                float h = og * tanhf(c);
                cvt_split(h, g_hsh[ci], g_hsl[ci]);
            }
            gsync();
        }

        // ===== cell_fn pre GEMM: 1080 items (15 la x 6 ks x 12 ntiles) =====
        for (int w = blockIdx.x; w < 1080; w += P) {
            const int la = w / 72;
            const int r  = w - la * 72;
            const int ks = r / 12;
            const int n0 = (r % 12) << 7;
            const int cc = (ks < 3) ? ks : (ks - 3);
            const __nv_bfloat16 *ah, *al, *bh, *bl;
            size_t woff = (size_t)la * N3Z * H_;
            if (ks < 3) {
                ah = g_hgh; al = g_hgl;
                bh = cWgh_h + woff; bl = cWgh_l + woff;
            } else {
                size_t o2 = (size_t)la * B_ * H_;
                ah = g_hsh + o2; al = g_hsl + o2;
                bh = cWgp_h + woff; bl = cWgp_l + woff;
            }
            float acc[4][4][4] = {};
            gemm_mma(ah, al, H_, bh, bl, H_, n0, c_ko[cc], c_kc[cc], usmem, acc);
            store_acc(g_pre3 + (size_t)ks * LABN3Z + (size_t)la * B_ * N3Z,
                      N3Z, n0, acc);
        }
        gsync();

        // ===== cell_fn pointwise: sum 6 partials, write icell/ccell hi/lo ===
        for (int idx = gtid; idx < LABZ; idx += gthreads) {
            int la = idx / (B_*Z_);
            int r  = idx - la * (B_*Z_);
            int z  = r % Z_;
            size_t base = ((size_t)la * B_ + (r / Z_)) * N3Z;
            const float* bb = bg + (size_t)la * N3Z;
            float vi = bb[0*Z_ + z], vf = bb[1*Z_ + z], vg = bb[2*Z_ + z];
            #pragma unroll
            for (int ks = 0; ks < 6; ++ks) {
                const float* p = g_pre3 + (size_t)ks * LABN3Z + base;
                vi += p[0*Z_ + z];
                vf += p[1*Z_ + z];
                vg += p[2*Z_ + z];
            }
            float ig = sigmoidf_(vi);
            float fg = sigmoidf_(vf);
            float gg = tanhf(vg);
            float ic = ig * g_cs[idx];
            float cc2 = fg * gg + ic;
            cvt_split(ic,  g_ich[idx], g_icl[idx]);
            cvt_split(cc2, g_cch[idx], g_ccl[idx]);
        }
        gsync();

        // ===== t1/t2 GEMM: 240 items (15 la x {t1,t2} x 2 ks x 4 ntiles) ====
        for (int w = blockIdx.x; w < 240; w += P) {
            const int la = w / 16;
            const int r  = w - la * 16;
            const int which = r >> 3;
            const int rr = r & 7;
            const int ks = rr >> 2;
            const int n0 = (rr & 3) << 7;
            size_t ao = (size_t)la * B_ * Z_;
            const __nv_bfloat16* ah = (which ? g_cch : g_ich) + ao;
            const __nv_bfloat16* al = (which ? g_ccl : g_icl) + ao;
            size_t woff = (size_t)la * Z_ * Z_;
            float acc[4][4][4] = {};
            gemm_mma(ah, al, Z_, cWilc_h + woff, cWilc_l + woff, Z_,
                     n0, ks * 256, 256, usmem, acc);
            store_acc((which ? g_t2p : g_t1p)
                      + (size_t)ks * LABZ + (size_t)la * B_ * Z_,
                      Z_, n0, acc);
        }
        gsync();

        // ===== combine: sum axes+ks, sigmoid(t2)*softmax(t1) -> cat hi/lo ===
        for (int row = blockIdx.x; row < L_*B_; row += P) {
            const int l = row / B_, b = row % B_;
            float t1v[2], t2v[2];
            #pragma unroll
            for (int h = 0; h < 2; ++h) {
                const int y = tid + h*256;
                float sb = bilc[(size_t)(l*A_+0)*Z_ + y]
                         + bilc[(size_t)(l*A_+1)*Z_ + y]
                         + bilc[(size_t)(l*A_+2)*Z_ + y];
                size_t off = (size_t)(l*A_) * B_ * Z_ + (size_t)b * Z_ + y;
                size_t st  = (size_t)B_ * Z_;
                const float* p1 = g_t1p + off;
                const float* p2 = g_t2p + off;
                t1v[h] = p1[0] + p1[st] + p1[2*st]
                       + p1[LABZ] + p1[LABZ+st] + p1[LABZ+2*st] + sb;
                t2v[h] = p2[0] + p2[st] + p2[2*st]
                       + p2[LABZ] + p2[LABZ+st] + p2[LABZ+2*st] + sb;
            }
            red[tid] = fmaxf(t1v[0], t1v[1]);
            __syncthreads();
            for (int s = 128; s > 0; s >>= 1) {
                if (tid < s) red[tid] = fmaxf(red[tid], red[tid + s]);
                __syncthreads();
            }
            float M = red[0];
            __syncthreads();
            float e0 = expf(t1v[0] - M), e1 = expf(t1v[1] - M);
            red[tid] = e0 + e1;
            __syncthreads();
            for (int s = 128; s > 0; s >>= 1) {
                if (tid < s) red[tid] += red[tid + s];
                __syncthreads();
            }
            float inv = 1.f / red[0];
            __syncthreads();
            size_t co = (size_t)b * LZ + (size_t)l * Z_;
            float v0 = sigmoidf_(t2v[0]) * e0 * inv;
            float v1 = sigmoidf_(t2v[1]) * e1 * inv;
            cvt_split(v0, g_cath[co + tid],       g_catl[co + tid]);
            cvt_split(v1, g_cath[co + tid + 256], g_catl[co + tid + 256]);
        }
        gsync();

        // ===== single_li GEMM: 40 items (10 K-chunks x 4 ntiles) =====
        for (int w = blockIdx.x; w < 40; w += P) {
            const int ks = w >> 2;
            const int n0 = (w & 3) << 7;
            float acc[4][4][4] = {};
            gemm_mma(g_cath, g_catl, LZ, cWsl_h, cWsl_l, LZ,
                     n0, ks * 256, 256, usmem, acc);
            store_acc(g_hgp + (size_t)ks * B_ * H_, H_, n0, acc);
        }
        gsync();

        // ===== reduce 10 splits + bias -> h_g (+hi/lo); convert x[t+1] =====
        for (int idx = gtid; idx < B_*H_; idx += gthreads) {
            float s = bsl[idx % H_];
            #pragma unroll
            for (int ks = 0; ks < 10; ++ks) s += g_hgp[(size_t)ks * B_ * H_ + idx];
            g_hg[idx] = s;
            cvt_split(s, g_hgh[idx], g_hgl[idx]);
            if (t + 1 < T_)
                cvt_split(x[(size_t)(t+1) * B_ * H_ + idx],
                          g_xh[idx], g_xl[idx]);
        }
        gsync();
    }

    // ===== final y for t = T-1 =====
    for (int w = blockIdx.x; w < 16; w += P) {
        const int warp = tid >> 5, lane = tid & 31;
        const int b    = w * 8 + warp;
        const float* h  = g_hg + (size_t)b * H_;
        const float* wl = Wlin + (size_t)(T_-1) * H_;
        float s = 0.f;
        for (int k = lane; k < H_; k += 32) s = fmaf(h[k], wl[k], s);
        #pragma unroll
        for (int o2 = 16; o2 > 0; o2 >>= 1) s += __shfl_down_sync(0xffffffffu, s, o2);
        if (lane == 0) out[(size_t)(T_-1) * B_ + b] = s + blin[T_-1];
    }
}

// ---------------- host orchestration ---------------------------------------
extern "C" void kernel_launch(void* const* d_in, const int* in_sizes, int n_in,
                              void* d_out, int out_size)
{
    const float* x      = (const float*)d_in[0];
    const float* Wx     = (const float*)d_in[1];
    const float* Wh     = (const float*)d_in[2];
    const float* b_lstm = (const float*)d_in[3];
    const float* Wg_h   = (const float*)d_in[4];
    const float* Wg_p   = (const float*)d_in[5];
    const float* bg     = (const float*)d_in[6];
    const float* Wilc   = (const float*)d_in[7];
    const float* bilc   = (const float*)d_in[8];
    const float* Wsl    = (const float*)d_in[9];
    const float* bsl    = (const float*)d_in[10];
    const float* Wlin   = (const float*)d_in[11];
    const float* blin   = (const float*)d_in[12];
    float* out = (float*)d_out;

    cudaFuncSetAttribute(k_persist, cudaFuncAttributeMaxDynamicSharedMemorySize,
                         SMEM_DYN);

    // Safe co-resident grid size (recomputed every call; deterministic).
    int dev = 0;
    cudaGetDevice(&dev);
    int sms = 148;
    cudaDeviceGetAttribute(&sms, cudaDevAttrMultiProcessorCount, dev);
    int bpm = 1;
    cudaOccupancyMaxActiveBlocksPerMultiprocessor(&bpm, k_persist, 256, SMEM_DYN);
    if (bpm < 1) bpm = 1;
    if (bpm > 2) bpm = 2;
    int P = sms * bpm;

    k_persist<<<P, 256, SMEM_DYN>>>(x, Wx, Wh, b_lstm, Wg_h, Wg_p, bg, Wilc,
                                    bilc, Wsl, bsl, Wlin, blin, out);
}

// round 16
// speedup vs baseline: 2.7649x; 1.0349x over previous
#include <cuda_runtime.h>
#include <cuda_bf16.h>
#include <math.h>
#include <stdint.h>

#define T_ 64
#define B_ 128
#define H_ 512
#define A_ 3
#define L_ 5
#define Z_ 512
#define NH4 (4*H_)      /* 2048 */
#define N3Z (3*Z_)      /* 1536 */
#define LZ  (L_*Z_)     /* 2560 */

#define ABNH4  (A_*B_*NH4)
#define LABZ   (L_*A_*B_*Z_)
#define LABN3Z (L_*A_*B_*N3Z)
#define LABH   (L_*A_*B_*H_)

#define NWX   (A_*L_*4*H_*H_)      /* 15728640 */
#define NWG   (L_*A_*3*Z_*H_)      /* 11796480 */
#define NWILC (L_*A_*Z_*Z_)        /* 3932160  */
#define NWSL  (H_*LZ)              /* 1310720  */

#define NT   512                    /* threads per CTA */
#define KC   32                     /* K chunk staged in smem */
#define APAD 8
#define ASTR (KC + APAD)            /* 40 elems = 80 B row stride */
#define TAB  (128*ASTR*2)           /* A tile bytes: 10240 */
#define TBB  (256*ASTR*2)           /* B tile bytes: 20480 */
#define BOFF (2*TAB)                /* B tiles offset within stage */
#define STAGE_BYTES (2*TAB + 2*TBB) /* 61440 */
#define SMEM_DYN (3*STAGE_BYTES)    /* 184320 */

// ---------------- persistent scratch (device globals; no allocation) -------
__device__ float g_cs[LABH];
__device__ float g_hg[B_*H_];
__device__ float g_prep[6*ABNH4];
__device__ float g_pre3[6*LABN3Z];
__device__ float g_t1p[2*LABZ];
__device__ float g_t2p[2*LABZ];
__device__ float g_hgp[10*B_*H_];

// pre-converted activations (bf16 hi/lo)
__device__ __nv_bfloat16 g_xh[B_*H_],  g_xl[B_*H_];
__device__ __nv_bfloat16 g_hsh[LABH],  g_hsl[LABH];
__device__ __nv_bfloat16 g_hgh[B_*H_], g_hgl[B_*H_];
__device__ __nv_bfloat16 g_ich[LABZ],  g_icl[LABZ];
__device__ __nv_bfloat16 g_cch[LABZ],  g_ccl[LABZ];
__device__ __nv_bfloat16 g_cath[B_*LZ], g_catl[B_*LZ];

// pre-split bf16 weights (hi/lo), converted once per launch
__device__ __nv_bfloat16 cWx_h[NWX],   cWx_l[NWX];
__device__ __nv_bfloat16 cWh_h[NWX],   cWh_l[NWX];
__device__ __nv_bfloat16 cWgh_h[NWG],  cWgh_l[NWG];
__device__ __nv_bfloat16 cWgp_h[NWG],  cWgp_l[NWG];
__device__ __nv_bfloat16 cWilc_h[NWILC], cWilc_l[NWILC];   // TRANSPOSED [la][y][z]
__device__ __nv_bfloat16 cWsl_h[NWSL], cWsl_l[NWSL];

// ---------------- grid barrier ---------------------------------------------
__device__ unsigned g_cnt = 0;
__device__ volatile unsigned g_gen = 0;

__device__ __forceinline__ void gsync() {
    __syncthreads();
    if (threadIdx.x == 0) {
        unsigned gen = g_gen;
        __threadfence();
        if (atomicAdd(&g_cnt, 1u) == gridDim.x - 1) {
            g_cnt = 0;
            __threadfence();
            g_gen = gen + 1u;
        } else {
            while (g_gen == gen) { __nanosleep(32); }
        }
        __threadfence();
    }
    __syncthreads();
}

__device__ __forceinline__ float sigmoidf_(float x) { return 1.f / (1.f + expf(-x)); }

__device__ __forceinline__ void cvt_split(float x, __nv_bfloat16& h, __nv_bfloat16& l) {
    h = __float2bfloat16_rn(x);
    l = __float2bfloat16_rn(x - __bfloat162float(h));
}

__device__ __forceinline__ uint32_t smem_u32(const void* p) {
    uint32_t a;
    asm("{ .reg .u64 t; cvta.to.shared.u64 t, %1; cvt.u32.u64 %0, t; }"
        : "=r"(a) : "l"(p));
    return a;
}

// ---------------- cp.async + tensor ops (all baseline sm_80+) --------------
__device__ __forceinline__ void cp16(uint32_t dst, const void* src) {
    asm volatile("cp.async.cg.shared.global [%0], [%1], 16;"
        :: "r"(dst), "l"(src) : "memory");
}
#define CP_COMMIT() asm volatile("cp.async.commit_group;" ::: "memory")
#define CP_WAIT(n)  asm volatile("cp.async.wait_group %0;" :: "n"(n) : "memory")

__device__ __forceinline__ void ldm4(uint32_t* r, uint32_t addr) {
    asm volatile("ldmatrix.sync.aligned.m8n8.x4.shared.b16 {%0,%1,%2,%3}, [%4];"
        : "=r"(r[0]), "=r"(r[1]), "=r"(r[2]), "=r"(r[3]) : "r"(addr));
}
__device__ __forceinline__ void mma_bf16(float* c, const uint32_t* a,
                                         const uint32_t* b) {
    asm volatile(
        "mma.sync.aligned.m16n8k16.row.col.f32.bf16.bf16.f32 "
        "{%0,%1,%2,%3}, {%4,%5,%6,%7}, {%8,%9}, {%0,%1,%2,%3};"
        : "+f"(c[0]), "+f"(c[1]), "+f"(c[2]), "+f"(c[3])
        : "r"(a[0]), "r"(a[1]), "r"(a[2]), "r"(a[3]), "r"(b[0]), "r"(b[1]));
}

// stage one KC=32 chunk: A (128 rows) hi/lo + B (256 rows) hi/lo, 6 cp16/thr
__device__ __forceinline__ void stage_chunk(
    const __nv_bfloat16* __restrict__ Ah, const __nv_bfloat16* __restrict__ Al,
    int lda,
    const __nv_bfloat16* __restrict__ Bh, const __nv_bfloat16* __restrict__ Bl,
    int ldb, int n0, int k0, uint32_t ubuf)
{
    const int t = threadIdx.x;
    // A: 512 granules per tile (128 rows x 4 cols of 8 elems)
    const int ar = t >> 2, ac = (t & 3) << 3;
    uint32_t da = ubuf + (uint32_t)(ar * ASTR + ac) * 2;
    cp16(da,       Ah + (size_t)ar * lda + k0 + ac);
    cp16(da + TAB, Al + (size_t)ar * lda + k0 + ac);
    // B: 1024 granules per tile (256 rows x 4): 2 per thread
    #pragma unroll
    for (int i = 0; i < 2; ++i) {
        const int g = t + i * NT;
        const int br = g >> 2, bc = (g & 3) << 3;
        uint32_t db = ubuf + BOFF + (uint32_t)(br * ASTR + bc) * 2;
        cp16(db,       Bh + (size_t)(n0 + br) * ldb + k0 + bc);
        cp16(db + TBB, Bl + (size_t)(n0 + br) * ldb + k0 + bc);
    }
}

// ---------------- GEMM core: 128x256 tile, 16 warps (2m x 8n) --------------
// 3-stage cp.async pipeline, single __syncthreads per chunk.
__device__ __forceinline__ void gemm_mma(
    const __nv_bfloat16* __restrict__ Ah, const __nv_bfloat16* __restrict__ Al,
    int lda,
    const __nv_bfloat16* __restrict__ Bh, const __nv_bfloat16* __restrict__ Bl,
    int ldb, int n0, int kbase, int kcnt, uint32_t usmem,
    float (&acc)[4][4][4])
{
    const int tid  = threadIdx.x;
    const int lane = tid & 31, wid = tid >> 5;
    const int wm = (wid & 1) << 6;          // 0 / 64
    const int wn = (wid >> 1) << 5;         // 0..224
    const int lrow = (lane & 7) + ((lane >> 3) & 1) * 8;
    const int lko  = (lane >> 4) * 8;

    const int nch = kcnt / KC;
    stage_chunk(Ah, Al, lda, Bh, Bl, ldb, n0, kbase, usmem);
    CP_COMMIT();
    for (int ch = 0; ch < nch; ++ch) {
        if (ch + 1 < nch) {
            stage_chunk(Ah, Al, lda, Bh, Bl, ldb, n0, kbase + (ch+1)*KC,
                        usmem + ((ch+1) % 3) * STAGE_BYTES);
            CP_COMMIT();
            CP_WAIT(1);
        } else {
            CP_WAIT(0);
        }
        __syncthreads();
        const uint32_t ub  = usmem + (ch % 3) * STAGE_BYTES;
        const uint32_t uAh = ub;
        const uint32_t uAl = ub + TAB;
        const uint32_t uBh = ub + BOFF;
        const uint32_t uBl = ub + BOFF + TBB;
        #pragma unroll
        for (int kk = 0; kk < KC; kk += 16) {
            uint32_t aH[4][4], aL[4][4], bH[4][2], bL[4][2];
            #pragma unroll
            for (int mf = 0; mf < 4; ++mf) {
                uint32_t off = (uint32_t)((wm + mf*16 + lrow) * ASTR + kk + lko) * 2;
                ldm4(aH[mf], uAh + off);
                ldm4(aL[mf], uAl + off);
            }
            #pragma unroll
            for (int np = 0; np < 2; ++np) {
                uint32_t off = (uint32_t)((wn + np*16 + lrow) * ASTR + kk + lko) * 2;
                uint32_t r[4];
                ldm4(r, uBh + off);
                bH[np*2][0] = r[0]; bH[np*2+1][0] = r[1];
                bH[np*2][1] = r[2]; bH[np*2+1][1] = r[3];
                ldm4(r, uBl + off);
                bL[np*2][0] = r[0]; bL[np*2+1][0] = r[1];
                bL[np*2][1] = r[2]; bL[np*2+1][1] = r[3];
            }
            #pragma unroll
            for (int mf = 0; mf < 4; ++mf)
                #pragma unroll
                for (int nf = 0; nf < 4; ++nf) {
                    mma_bf16(acc[mf][nf], aH[mf], bH[nf]);
                    mma_bf16(acc[mf][nf], aH[mf], bL[nf]);
                    mma_bf16(acc[mf][nf], aL[mf], bH[nf]);
                }
        }
    }
    __syncthreads();   // protect buffers before next item stages
}

__device__ __forceinline__ void store_acc(
    float* __restrict__ dst, int ldo, int n0, float (&acc)[4][4][4])
{
    const int lane = threadIdx.x & 31, wid = threadIdx.x >> 5;
    const int wm = (wid & 1) << 6, wn = (wid >> 1) << 5;
    const int g = lane >> 2, i2 = (lane & 3) << 1;
    #pragma unroll
    for (int mf = 0; mf < 4; ++mf) {
        const int r0 = wm + mf*16 + g;
        #pragma unroll
        for (int nf = 0; nf < 4; ++nf) {
            const int col = n0 + wn + nf*8 + i2;
            *(float2*)(dst + (size_t)r0 * ldo + col)
                = make_float2(acc[mf][nf][0], acc[mf][nf][1]);
            *(float2*)(dst + (size_t)(r0 + 8) * ldo + col)
                = make_float2(acc[mf][nf][2], acc[mf][nf][3]);
        }
    }
}

// K chunk tables: 512 -> {192,192,128} (multiples of KC)
__device__ __constant__ int c_ko[3] = {0, 192, 384};
__device__ __constant__ int c_kc[3] = {192, 192, 128};

// ---------------- the single persistent kernel ------------------------------
__global__ __launch_bounds__(NT, 1) void k_persist(
    const float* __restrict__ x,    const float* __restrict__ Wx,
    const float* __restrict__ Wh,   const float* __restrict__ b_lstm,
    const float* __restrict__ Wg_h, const float* __restrict__ Wg_p,
    const float* __restrict__ bg,   const float* __restrict__ Wilc,
    const float* __restrict__ bilc, const float* __restrict__ Wsl,
    const float* __restrict__ bsl,  const float* __restrict__ Wlin,
    const float* __restrict__ blin, float* __restrict__ out)
{
    extern __shared__ __align__(16) char dsm[];
    const uint32_t usmem = smem_u32(dsm);
    float* red = (float*)dsm;   // reduction scratch (combine stage)

    const int P   = gridDim.x;
    const int tid = threadIdx.x;
    const int gthreads = P * NT;
    const int gtid = blockIdx.x * NT + tid;
    const __nv_bfloat16 bz = __float2bfloat16_rn(0.f);

    // -------- init states + convert x[0] --------
    for (int i = gtid; i < LABH; i += gthreads) {
        g_cs[i] = 0.f; g_hsh[i] = bz; g_hsl[i] = bz;
    }
    for (int i = gtid; i < B_*H_; i += gthreads) {
        g_hg[i] = 0.f; g_hgh[i] = bz; g_hgl[i] = bz;
        cvt_split(x[i], g_xh[i], g_xl[i]);
    }

    // -------- weight pre-split (fp32 -> bf16 hi/lo) --------
    for (int i = gtid; i < NWX; i += gthreads) {
        cvt_split(Wx[i], cWx_h[i], cWx_l[i]);
        cvt_split(Wh[i], cWh_h[i], cWh_l[i]);
    }
    for (int i = gtid; i < NWG; i += gthreads) {
        cvt_split(Wg_h[i], cWgh_h[i], cWgh_l[i]);
        cvt_split(Wg_p[i], cWgp_h[i], cWgp_l[i]);
    }
    for (int i = gtid; i < NWSL; i += gthreads)
        cvt_split(Wsl[i], cWsl_h[i], cWsl_l[i]);
    for (int i = gtid; i < NWILC; i += gthreads) {
        int la = i / (Z_*Z_);
        int r  = i - la * (Z_*Z_);
        int y  = r / Z_, z = r - (r / Z_) * Z_;
        cvt_split(Wilc[(size_t)la * Z_ * Z_ + (size_t)z * Z_ + y],
                  cWilc_h[i], cWilc_l[i]);
    }
    gsync();

    for (int t = 0; t < T_; ++t) {
        // ===== Multi-LSTM levels =====
        for (int l = 0; l < L_; ++l) {
            // --- GEMM stage: 144 items (+8 y-items at l==0, t>0) ---
            const int extra = (l == 0 && t > 0) ? 8 : 0;
            for (int w = blockIdx.x; w < 144 + extra; w += P) {
                if (w < 144) {
                    const int ks = w / 24;            // 0..5
                    const int r  = w - ks * 24;
                    const int a  = r >> 3;
                    const int n0 = (r & 7) << 8;
                    const int cc = (ks < 3) ? ks : (ks - 3);
                    const __nv_bfloat16 *ah, *al, *bh, *bl;
                    size_t woff = (size_t)(a*L_ + l) * 4 * H_ * H_;
                    if (ks < 3) {
                        if (l == 0) { ah = g_xh; al = g_xl; }
                        else {
                            size_t o2 = ((size_t)(l-1)*A_ + a) * B_ * H_;
                            ah = g_hsh + o2; al = g_hsl + o2;
                        }
                        bh = cWx_h + woff; bl = cWx_l + woff;
                    } else {
                        size_t o2 = ((size_t)l*A_ + a) * B_ * H_;
                        ah = g_hsh + o2; al = g_hsl + o2;
                        bh = cWh_h + woff; bl = cWh_l + woff;
                    }
                    float acc[4][4][4] = {};
                    gemm_mma(ah, al, H_, bh, bl, H_, n0, c_ko[cc], c_kc[cc],
                             usmem, acc);
                    store_acc(g_prep + (size_t)ks * ABNH4 + (size_t)a * B_ * NH4,
                              NH4, n0, acc);
                } else {
                    const int j    = w - 144;         // 0..7
                    const int warp = tid >> 5, lane = tid & 31;
                    const int b    = j * 16 + warp;
                    const float* h  = g_hg + (size_t)b * H_;
                    const float* wl = Wlin + (size_t)(t-1) * H_;
                    float s = 0.f;
                    for (int k = lane; k < H_; k += 32) s = fmaf(h[k], wl[k], s);
                    #pragma unroll
                    for (int o2 = 16; o2 > 0; o2 >>= 1)
                        s += __shfl_down_sync(0xffffffffu, s, o2);
                    if (lane == 0) out[(size_t)(t-1) * B_ + b] = s + blin[t-1];
                }
            }
            gsync();

            // --- pointwise gates: sum 6 K-split partials, write hs hi/lo ---
            for (int idx = gtid; idx < A_*B_*H_; idx += gthreads) {
                int a = idx / (B_*H_);
                int r = idx - a * (B_*H_);
                int b = r / H_;
                int o = r - b * H_;
                size_t base = ((size_t)a * B_ + b) * NH4;
                const float* bb = b_lstm + ((size_t)(a*L_ + l)) * 4 * H_;
                float pi = bb[0*H_ + o], pf = bb[1*H_ + o];
                float pg = bb[2*H_ + o], po = bb[3*H_ + o];
                #pragma unroll
                for (int ks = 0; ks < 6; ++ks) {
                    const float* p = g_prep + (size_t)ks * ABNH4 + base;
                    pi += p[0*H_ + o];
                    pf += p[1*H_ + o];
                    pg += p[2*H_ + o];
                    po += p[3*H_ + o];
                }
                float ig = sigmoidf_(pi);
                float fg = sigmoidf_(pf);
                float gg = tanhf(pg);
                float og = sigmoidf_(po);
                size_t ci = ((size_t)(l*A_ + a) * B_ + b) * H_ + o;
                float c = fg * g_cs[ci] + ig * gg;
                g_cs[ci] = c;
                float h = og * tanhf(c);
                cvt_split(h, g_hsh[ci], g_hsl[ci]);
            }
            gsync();
        }

        // ===== cell_fn pre GEMM: 540 items (15 la x 6 ks x 6 ntiles) =====
        for (int w = blockIdx.x; w < 540; w += P) {
            const int la = w / 36;
            const int r  = w - la * 36;
            const int ks = r / 6;
            const int n0 = (r % 6) << 8;
            const int cc = (ks < 3) ? ks : (ks - 3);
            const __nv_bfloat16 *ah, *al, *bh, *bl;
            size_t woff = (size_t)la * N3Z * H_;
            if (ks < 3) {
                ah = g_hgh; al = g_hgl;
                bh = cWgh_h + woff; bl = cWgh_l + woff;
            } else {
                size_t o2 = (size_t)la * B_ * H_;
                ah = g_hsh + o2; al = g_hsl + o2;
                bh = cWgp_h + woff; bl = cWgp_l + woff;
            }
            float acc[4][4][4] = {};
            gemm_mma(ah, al, H_, bh, bl, H_, n0, c_ko[cc], c_kc[cc], usmem, acc);
            store_acc(g_pre3 + (size_t)ks * LABN3Z + (size_t)la * B_ * N3Z,
                      N3Z, n0, acc);
        }
        gsync();

        // ===== cell_fn pointwise: sum 6 partials, write icell/ccell hi/lo ===
        for (int idx = gtid; idx < LABZ; idx += gthreads) {
            int la = idx / (B_*Z_);
            int r  = idx - la * (B_*Z_);
            int z  = r % Z_;
            size_t base = ((size_t)la * B_ + (r / Z_)) * N3Z;
            const float* bb = bg + (size_t)la * N3Z;
            float vi = bb[0*Z_ + z], vf = bb[1*Z_ + z], vg = bb[2*Z_ + z];
            #pragma unroll
            for (int ks = 0; ks < 6; ++ks) {
                const float* p = g_pre3 + (size_t)ks * LABN3Z + base;
                vi += p[0*Z_ + z];
                vf += p[1*Z_ + z];
                vg += p[2*Z_ + z];
            }
            float ig = sigmoidf_(vi);
            float fg = sigmoidf_(vf);
            float gg = tanhf(vg);
            float ic = ig * g_cs[idx];
            float cc2 = fg * gg + ic;
            cvt_split(ic,  g_ich[idx], g_icl[idx]);
            cvt_split(cc2, g_cch[idx], g_ccl[idx]);
        }
        gsync();

        // ===== t1/t2 GEMM: 120 items (15 la x {t1,t2} x 2 ks x 2 ntiles) ====
        for (int w = blockIdx.x; w < 120; w += P) {
            const int la = w / 8;
            const int r  = w - la * 8;
            const int which = r >> 2;
            const int rr = r & 3;
            const int ks = rr >> 1;
            const int n0 = (rr & 1) << 8;
            size_t ao = (size_t)la * B_ * Z_;
            const __nv_bfloat16* ah = (which ? g_cch : g_ich) + ao;
            const __nv_bfloat16* al = (which ? g_ccl : g_icl) + ao;
            size_t woff = (size_t)la * Z_ * Z_;
            float acc[4][4][4] = {};
            gemm_mma(ah, al, Z_, cWilc_h + woff, cWilc_l + woff, Z_,
                     n0, ks * 256, 256, usmem, acc);
            store_acc((which ? g_t2p : g_t1p)
                      + (size_t)ks * LABZ + (size_t)la * B_ * Z_,
                      Z_, n0, acc);
        }
        gsync();

        // ===== combine: sum axes+ks, sigmoid(t2)*softmax(t1) -> cat hi/lo ===
        for (int row = blockIdx.x; row < L_*B_; row += P) {
            const int l = row / B_, b = row % B_;
            const int y = tid;                       // 512 threads = Z
            float sb = bilc[(size_t)(l*A_+0)*Z_ + y]
                     + bilc[(size_t)(l*A_+1)*Z_ + y]
                     + bilc[(size_t)(l*A_+2)*Z_ + y];
            size_t off = (size_t)(l*A_) * B_ * Z_ + (size_t)b * Z_ + y;
            size_t st  = (size_t)B_ * Z_;
            const float* p1 = g_t1p + off;
            const float* p2 = g_t2p + off;
            float t1v = p1[0] + p1[st] + p1[2*st]
                      + p1[LABZ] + p1[LABZ+st] + p1[LABZ+2*st] + sb;
            float t2v = p2[0] + p2[st] + p2[2*st]
                      + p2[LABZ] + p2[LABZ+st] + p2[LABZ+2*st] + sb;
            red[tid] = t1v;
            __syncthreads();
            for (int s = 256; s > 0; s >>= 1) {
                if (tid < s) red[tid] = fmaxf(red[tid], red[tid + s]);
                __syncthreads();
            }
            float M = red[0];
            __syncthreads();
            float e0 = expf(t1v - M);
            red[tid] = e0;
            __syncthreads();
            for (int s = 256; s > 0; s >>= 1) {
                if (tid < s) red[tid] += red[tid + s];
                __syncthreads();
            }
            float inv = 1.f / red[0];
            __syncthreads();
            size_t co = (size_t)b * LZ + (size_t)l * Z_;
            float v0 = sigmoidf_(t2v) * e0 * inv;
            cvt_split(v0, g_cath[co + y], g_catl[co + y]);
        }
        gsync();

        // ===== single_li GEMM: 20 items (10 K-chunks x 2 ntiles) =====
        for (int w = blockIdx.x; w < 20; w += P) {
            const int ks = w >> 1;
            const int n0 = (w & 1) << 8;
            float acc[4][4][4] = {};
            gemm_mma(g_cath, g_catl, LZ, cWsl_h, cWsl_l, LZ,
                     n0, ks * 256, 256, usmem, acc);
            store_acc(g_hgp + (size_t)ks * B_ * H_, H_, n0, acc);
        }
        gsync();

        // ===== reduce 10 splits + bias -> h_g (+hi/lo); convert x[t+1] =====
        for (int idx = gtid; idx < B_*H_; idx += gthreads) {
            float s = bsl[idx % H_];
            #pragma unroll
            for (int ks = 0; ks < 10; ++ks) s += g_hgp[(size_t)ks * B_ * H_ + idx];
            g_hg[idx] = s;
            cvt_split(s, g_hgh[idx], g_hgl[idx]);
            if (t + 1 < T_)
                cvt_split(x[(size_t)(t+1) * B_ * H_ + idx],
                          g_xh[idx], g_xl[idx]);
        }
        gsync();
    }

    // ===== final y for t = T-1 =====
    for (int w = blockIdx.x; w < 8; w += P) {
        const int warp = tid >> 5, lane = tid & 31;
        const int b    = w * 16 + warp;
        const float* h  = g_hg + (size_t)b * H_;
        const float* wl = Wlin + (size_t)(T_-1) * H_;
        float s = 0.f;
        for (int k = lane; k < H_; k += 32) s = fmaf(h[k], wl[k], s);
        #pragma unroll
        for (int o2 = 16; o2 > 0; o2 >>= 1) s += __shfl_down_sync(0xffffffffu, s, o2);
        if (lane == 0) out[(size_t)(T_-1) * B_ + b] = s + blin[T_-1];
    }
}

// ---------------- host orchestration ---------------------------------------
extern "C" void kernel_launch(void* const* d_in, const int* in_sizes, int n_in,
                              void* d_out, int out_size)
{
    const float* x      = (const float*)d_in[0];
    const float* Wx     = (const float*)d_in[1];
    const float* Wh     = (const float*)d_in[2];
    const float* b_lstm = (const float*)d_in[3];
    const float* Wg_h   = (const float*)d_in[4];
    const float* Wg_p   = (const float*)d_in[5];
    const float* bg     = (const float*)d_in[6];
    const float* Wilc   = (const float*)d_in[7];
    const float* bilc   = (const float*)d_in[8];
    const float* Wsl    = (const float*)d_in[9];
    const float* bsl    = (const float*)d_in[10];
    const float* Wlin   = (const float*)d_in[11];
    const float* blin   = (const float*)d_in[12];
    float* out = (float*)d_out;

    cudaFuncSetAttribute(k_persist, cudaFuncAttributeMaxDynamicSharedMemorySize,
                         SMEM_DYN);

    // Safe co-resident grid size (recomputed every call; deterministic).
    int dev = 0;
    cudaGetDevice(&dev);
    int sms = 148;
    cudaDeviceGetAttribute(&sms, cudaDevAttrMultiProcessorCount, dev);
    int bpm = 1;
    cudaOccupancyMaxActiveBlocksPerMultiprocessor(&bpm, k_persist, NT, SMEM_DYN);
    if (bpm < 1) bpm = 1;
    if (bpm > 1) bpm = 1;
    int P = sms * bpm;

    k_persist<<<P, NT, SMEM_DYN>>>(x, Wx, Wh, b_lstm, Wg_h, Wg_p, bg, Wilc,
                                   bilc, Wsl, bsl, Wlin, blin, out);
}